// round 6
// baseline (speedup 1.0000x reference)
#include <cuda_runtime.h>
#include <cstdint>

// Problem constants (fixed by the dataset)
constexpr int BB   = 16;     // batch
constexpr int NTOK = 16384;  // tokens
constexpr int DD   = 64;     // model dim (= dhf)
constexpr int GG   = 256;    // groups
constexpr int CC   = 64;     // tokens per group
constexpr int NH   = 4;      // heads
// SCALE = 4.0 multiplies scores; folded into Q (exact: power of two)

#define LDSF 68  // smem row stride in floats

// ---------------- scratch (no allocations allowed) ----------------
__device__ float g_pooled[BB * GG * DD];      // 1 MiB
__device__ float g_qkv[3 * BB * GG * DD];     // 3 MiB  [q/k/v][b][n][d]
__device__ float g_inter[BB * GG * DD];       // 1 MiB

// ---------------- tf32 mma helpers ----------------
__device__ __forceinline__ uint32_t tf32r(float f) {
    uint32_t u; asm("cvt.rna.tf32.f32 %0, %1;" : "=r"(u) : "f"(f)); return u;
}
__device__ __forceinline__ float tf32f(float f) { return __uint_as_float(tf32r(f)); }
__device__ __forceinline__ uint32_t uf(float f) { return __float_as_uint(f); }

__device__ __forceinline__ void mma8(float c[4],
    uint32_t a0, uint32_t a1, uint32_t a2, uint32_t a3, uint32_t b0, uint32_t b1) {
    asm("mma.sync.aligned.m16n8k8.row.col.f32.tf32.tf32.f32 "
        "{%0,%1,%2,%3}, {%4,%5,%6,%7}, {%8,%9}, {%0,%1,%2,%3};"
        : "+f"(c[0]), "+f"(c[1]), "+f"(c[2]), "+f"(c[3])
        : "r"(a0), "r"(a1), "r"(a2), "r"(a3), "r"(b0), "r"(b1));
}

// Column permutation within each 8-block: P(c) = (c&~7) | ((c&3)<<1) | (c>>2).
// Makes fragment pairs (c, c+4) physically adjacent -> float2 LDS.

// stage 64x64 row-major weight matrix into permuted smem (tf32), 512 threads
__device__ __forceinline__ void stageWp(const float* __restrict__ W, float* ws, int tid) {
#pragma unroll
    for (int k = 0; k < 2; ++k) {
        int f = tid + 512 * k;          // float4 index 0..1023
        int r = f >> 4, c4 = f & 15;
        float4 v = ((const float4*)(W + r * 64))[c4];
        // logical cols 4c4..4c4+3 -> physical base + {0,2,4,6}
        float* dst = ws + r * LDSF + ((4 * c4) & ~7) + (((4 * c4) & 4) >> 2);
        dst[0] = tf32f(v.x); dst[2] = tf32f(v.y); dst[4] = tf32f(v.z); dst[6] = tf32f(v.w);
    }
}

// ---------------- Kernel 1: intra-group MHA (tf32 tensor cores) ----------------
// grid = 4096 (b*256+g), 512 threads = 16 warps, dyn smem = 6*64*LDSF*4 = 104448 B
__global__ __launch_bounds__(512, 2) void intra_kernel(
    const float* __restrict__ x, const int* __restrict__ part,
    const float* __restrict__ Wq, const float* __restrict__ bq,
    const float* __restrict__ Wk, const float* __restrict__ bk,
    const float* __restrict__ Wv, const float* __restrict__ bv,
    const float* __restrict__ Wo, const float* __restrict__ bo,
    float* __restrict__ out)
{
    extern __shared__ float sm[];
    float* xs = sm;                 // tf32 x (perm); later attn-out (perm)
    float* qs = sm + 1 * 64 * LDSF; // tf32 q (perm, pre-scaled by 4); later fp32 stash (logical)
    float* ks = sm + 2 * 64 * LDSF; // tf32 k (perm)
    float* vs = sm + 3 * 64 * LDSF; // tf32 v (perm)
    float* wA = sm + 4 * 64 * LDSF; // weight stage A / probs head-even
    float* wB = sm + 5 * 64 * LDSF; // weight stage B / probs head-odd

    const int tid = threadIdx.x;
    const int bb = blockIdx.x >> 8;
    const int g  = blockIdx.x & 255;
    const int* pg = part + (size_t)g * CC;
    const float* xb = x + (size_t)bb * NTOK * DD;

    const int lane = tid & 31, w = tid >> 5;
    const int r  = lane >> 2;        // fragment group id (0..7)
    const int cc = lane & 3;         // thread-in-group (0..3)
    // physical offsets for C-fragment logical cols 2cc, 2cc+1
    const int c0l = 2 * cc, c1l = 2 * cc + 1;
    const int pc0 = ((c0l & 3) << 1) | (c0l >> 2);
    const int pc1 = ((c1l & 3) << 1) | (c1l >> 2);
    const int pr  = ((r & 3) << 1) | (r >> 2);   // P within 8-block of r

    // ---- gather 64 token rows (tf32, permuted) + stage Wq ----
#pragma unroll
    for (int k = 0; k < 2; ++k) {
        int f = tid + 512 * k;
        int row = f >> 4, c4 = f & 15;
        int tok = pg[row];
        float4 v = ((const float4*)(xb + (size_t)tok * DD))[c4];
        float* dst = xs + row * LDSF + ((4 * c4) & ~7) + (((4 * c4) & 4) >> 2);
        dst[0] = tf32f(v.x); dst[2] = tf32f(v.y); dst[4] = tf32f(v.z); dst[6] = tf32f(v.w);
    }
    stageWp(Wq, wA, tid);
    __syncthreads();

    // QKV warp tiling: mt = w&3 (rows 16mt), nqt = w>>2 (cols 16*nqt)
    const int mt = w & 3, nqt = w >> 2;
    const int row0 = 16 * mt + r;

    // ---- projection macro-ish lambda: D = A @ W^T + bias (optionally *4) ----
    auto proj = [&](const float* A, const float* Wm, const float* bias, float* D, bool scale4) {
        float acc[2][4] = {};
#pragma unroll
        for (int kt = 0; kt < 8; ++kt) {
            const int k0 = 8 * kt + 2 * cc;
            float2 aLo = *(const float2*)&A[row0 * LDSF + k0];
            float2 aHi = *(const float2*)&A[(row0 + 8) * LDSF + k0];
            uint32_t a0 = uf(aLo.x), a1 = uf(aHi.x), a2 = uf(aLo.y), a3 = uf(aHi.y);
#pragma unroll
            for (int nt = 0; nt < 2; ++nt) {
                const int n0 = 16 * nqt + 8 * nt;
                float2 bv = *(const float2*)&Wm[(n0 + r) * LDSF + k0];
                mma8(acc[nt], a0, a1, a2, a3, uf(bv.x), uf(bv.y));
            }
        }
#pragma unroll
        for (int nt = 0; nt < 2; ++nt) {
            const int n0 = 16 * nqt + 8 * nt;
            float b0v = bias[n0 + c0l], b1v = bias[n0 + c1l];
            float v0 = acc[nt][0] + b0v, v1 = acc[nt][1] + b1v;
            float v2 = acc[nt][2] + b0v, v3 = acc[nt][3] + b1v;
            if (scale4) { v0 *= 4.f; v1 *= 4.f; v2 *= 4.f; v3 *= 4.f; }
            D[row0 * LDSF + n0 + pc0]       = tf32f(v0);
            D[row0 * LDSF + n0 + pc1]       = tf32f(v1);
            D[(row0 + 8) * LDSF + n0 + pc0] = tf32f(v2);
            D[(row0 + 8) * LDSF + n0 + pc1] = tf32f(v3);
        }
    };

    // ---- Q (scaled by 4), overlap staging Wk ----
    proj(xs, wA, bq, qs, true);
    stageWp(Wk, wB, tid);
    __syncthreads();
    // ---- K, overlap staging Wv ----
    proj(xs, wB, bk, ks, false);
    stageWp(Wv, wA, tid);
    __syncthreads();
    // ---- V ----
    proj(xs, wA, bv, vs, false);
    __syncthreads();

    // ---- attention: 2 heads per pass (probs in wA / wB) ----
#pragma unroll 1
    for (int hp = 0; hp < 2; ++hp) {
        // scores: hsel = w>>3, smt = (w>>1)&3, snh = w&1 (cols 32*snh)
        {
            const int hsel = w >> 3, smt = (w >> 1) & 3, snh = w & 1;
            float* pb = hsel ? wB : wA;
            const int hq = (2 * hp + hsel) * 16;
            const int srow0 = 16 * smt + r;
            float acc[4][4] = {};
#pragma unroll
            for (int kt = 0; kt < 2; ++kt) {
                const int k0 = hq + 8 * kt + 2 * cc;
                float2 aLo = *(const float2*)&qs[srow0 * LDSF + k0];
                float2 aHi = *(const float2*)&qs[(srow0 + 8) * LDSF + k0];
                uint32_t a0 = uf(aLo.x), a1 = uf(aHi.x), a2 = uf(aLo.y), a3 = uf(aHi.y);
#pragma unroll
                for (int nt = 0; nt < 4; ++nt) {
                    const int n0 = 32 * snh + 8 * nt;
                    float2 bv = *(const float2*)&ks[(n0 + r) * LDSF + k0];
                    mma8(acc[nt], a0, a1, a2, a3, uf(bv.x), uf(bv.y));
                }
            }
#pragma unroll
            for (int nt = 0; nt < 4; ++nt) {
                const int n0 = 32 * snh + 8 * nt;
                pb[srow0 * LDSF + n0 + pc0]       = acc[nt][0];
                pb[srow0 * LDSF + n0 + pc1]       = acc[nt][1];
                pb[(srow0 + 8) * LDSF + n0 + pc0] = acc[nt][2];
                pb[(srow0 + 8) * LDSF + n0 + pc1] = acc[nt][3];
            }
        }
        __syncthreads();
        // softmax: 512 threads, 128 rows (2 bufs x 64 rows), 4 threads/row.
        // Row order is permuted in smem but max/sum are order-invariant.
        {
            float* pb = (tid & 256) ? wB : wA;
            const int row = (tid >> 2) & 63, seg = tid & 3;
            float* rr = pb + row * LDSF + seg * 16;
            float mx = rr[0];
#pragma unroll
            for (int m = 1; m < 16; ++m) mx = fmaxf(mx, rr[m]);
            mx = fmaxf(mx, __shfl_xor_sync(0xffffffffu, mx, 1));
            mx = fmaxf(mx, __shfl_xor_sync(0xffffffffu, mx, 2));
            float e[16];
            float sum = 0.f;
#pragma unroll
            for (int m = 0; m < 16; ++m) { e[m] = __expf(rr[m] - mx); sum += e[m]; }
            sum += __shfl_xor_sync(0xffffffffu, sum, 1);
            sum += __shfl_xor_sync(0xffffffffu, sum, 2);
            float inv = 1.f / sum;
#pragma unroll
            for (int m = 0; m < 16; ++m) rr[m] = tf32f(e[m] * inv);
        }
        __syncthreads();
        // AV: hsel = w>>3, amt = (w>>1)&3, anq = w&1; output cols hq + 8*anq + 0..7
        {
            const int hsel = w >> 3, amt = (w >> 1) & 3, anq = w & 1;
            float* pb = hsel ? wB : wA;
            const int hq = (2 * hp + hsel) * 16;
            const int arow0 = 16 * amt + r;
            const int nbase = hq + 8 * anq;
            float oacc[4] = {};
#pragma unroll
            for (int kt = 0; kt < 8; ++kt) {
                const int k0 = 8 * kt;
                float2 aLo = *(const float2*)&pb[arow0 * LDSF + k0 + 2 * cc];
                float2 aHi = *(const float2*)&pb[(arow0 + 8) * LDSF + k0 + 2 * cc];
                uint32_t b0 = uf(vs[(k0 + cc) * LDSF + nbase + pr]);
                uint32_t b1 = uf(vs[(k0 + cc + 4) * LDSF + nbase + pr]);
                mma8(oacc, uf(aLo.x), uf(aHi.x), uf(aLo.y), uf(aHi.y), b0, b1);
            }
            xs[arow0 * LDSF + nbase + pc0]       = tf32f(oacc[0]);
            xs[arow0 * LDSF + nbase + pc1]       = tf32f(oacc[1]);
            xs[(arow0 + 8) * LDSF + nbase + pc0] = tf32f(oacc[2]);
            xs[(arow0 + 8) * LDSF + nbase + pc1] = tf32f(oacc[3]);
        }
        __syncthreads();
    }

    // ---- stage Wo, then O projection -> gmem scatter + stash for pooled max ----
    stageWp(Wo, wA, tid);
    __syncthreads();
    {
        float acc[2][4] = {};
#pragma unroll
        for (int kt = 0; kt < 8; ++kt) {
            const int k0 = 8 * kt + 2 * cc;
            float2 aLo = *(const float2*)&xs[row0 * LDSF + k0];
            float2 aHi = *(const float2*)&xs[(row0 + 8) * LDSF + k0];
            uint32_t a0 = uf(aLo.x), a1 = uf(aHi.x), a2 = uf(aLo.y), a3 = uf(aHi.y);
#pragma unroll
            for (int nt = 0; nt < 2; ++nt) {
                const int n0 = 16 * nqt + 8 * nt;
                float2 bv = *(const float2*)&wA[(n0 + r) * LDSF + k0];
                mma8(acc[nt], a0, a1, a2, a3, uf(bv.x), uf(bv.y));
            }
        }
        const int tokA = pg[row0], tokB = pg[row0 + 8];
        float* oA = out + ((size_t)bb * NTOK + tokA) * DD;
        float* oB = out + ((size_t)bb * NTOK + tokB) * DD;
#pragma unroll
        for (int nt = 0; nt < 2; ++nt) {
            const int n0 = 16 * nqt + 8 * nt;
            float b0v = bo[n0 + c0l], b1v = bo[n0 + c1l];
            float v0 = acc[nt][0] + b0v, v1 = acc[nt][1] + b1v;
            float v2 = acc[nt][2] + b0v, v3 = acc[nt][3] + b1v;
            *(float2*)(oA + n0 + c0l) = make_float2(v0, v1);
            *(float2*)(oB + n0 + c0l) = make_float2(v2, v3);
            // stash (logical layout) for pooled max
            *(float2*)&qs[row0 * LDSF + n0 + c0l]       = make_float2(v0, v1);
            *(float2*)&qs[(row0 + 8) * LDSF + n0 + c0l] = make_float2(v2, v3);
        }
    }
    __syncthreads();
    if (tid < 64) {
        float m = qs[tid];
#pragma unroll 8
        for (int n = 1; n < 64; ++n) m = fmaxf(m, qs[n * LDSF + tid]);
        g_pooled[((size_t)bb * GG + g) * DD + tid] = m;
    }
}

// ---------------- helpers for fp32 inter path ----------------
__device__ __forceinline__ void fma16(float acc[4][4], const float4 a[4], const float4 w[4]) {
#pragma unroll
    for (int i = 0; i < 4; ++i)
#pragma unroll
        for (int j = 0; j < 4; ++j) {
            acc[i][j] = fmaf(a[i].x, w[j].x, acc[i][j]);
            acc[i][j] = fmaf(a[i].y, w[j].y, acc[i][j]);
            acc[i][j] = fmaf(a[i].z, w[j].z, acc[i][j]);
            acc[i][j] = fmaf(a[i].w, w[j].w, acc[i][j]);
        }
}

// ---------------- Kernel 2: inter QKV projections ----------------
__global__ __launch_bounds__(256) void inter_qkv_kernel(
    const float* __restrict__ Wq, const float* __restrict__ bq,
    const float* __restrict__ Wk, const float* __restrict__ bk,
    const float* __restrict__ Wv, const float* __restrict__ bv)
{
    __shared__ float As[64 * LDSF];
    __shared__ float ws[64 * LDSF];
    const int tid = threadIdx.x;
    const int blk = blockIdx.x;
    const int wsel = blk >> 6;
    const int b = (blk >> 2) & 15;
    const int quarter = blk & 3;
    const float* W = (wsel == 0) ? Wq : ((wsel == 1) ? Wk : Wv);
    const float* bias = (wsel == 0) ? bq : ((wsel == 1) ? bk : bv);
    const float* A = g_pooled + ((size_t)b * GG + quarter * 64) * DD;
    float* dst = g_qkv + ((size_t)(wsel * BB + b) * GG + quarter * 64) * DD;

#pragma unroll
    for (int k = 0; k < 4; ++k) {
        int f = tid + 256 * k;
        int r = f >> 4, c4 = f & 15;
        *(float4*)&As[r * LDSF + 4 * c4] = ((const float4*)(A + r * 64))[c4];
        *(float4*)&ws[r * LDSF + 4 * c4] = ((const float4*)(W + r * 64))[c4];
    }
    __syncthreads();

    const int tn = tid >> 4, to = tid & 15;
    float acc[4][4] = {};
#pragma unroll 4
    for (int d4 = 0; d4 < 64; d4 += 4) {
        float4 a[4], w[4];
#pragma unroll
        for (int i = 0; i < 4; ++i) a[i] = *(const float4*)&As[(4 * tn + i) * LDSF + d4];
#pragma unroll
        for (int j = 0; j < 4; ++j) w[j] = *(const float4*)&ws[(4 * to + j) * LDSF + d4];
        fma16(acc, a, w);
    }
    float bj[4];
#pragma unroll
    for (int j = 0; j < 4; ++j) bj[j] = bias[4 * to + j];
#pragma unroll
    for (int i = 0; i < 4; ++i) {
        float4 v;
        v.x = acc[i][0] + bj[0];
        v.y = acc[i][1] + bj[1];
        v.z = acc[i][2] + bj[2];
        v.w = acc[i][3] + bj[3];
        *(float4*)&dst[(4 * tn + i) * 64 + 4 * to] = v;
    }
}

// ---------------- Kernel 3: inter attention (+ O proj) ----------------
__global__ __launch_bounds__(128) void inter_attn_kernel(
    const float* __restrict__ Wo, const float* __restrict__ bo)
{
    extern __shared__ float sm2[];
    float* ksm = sm2;
    float* vsm = sm2 + 256 * LDSF;
    float* ss  = sm2 + 2 * 256 * LDSF;  // 4 * 264
    float* sq  = ss + 4 * 264;          // 64
    float* so  = sq + 64;               // 64

    const int tid = threadIdx.x;
    const int b = blockIdx.x >> 4;
    const int chunk = blockIdx.x & 15;

    const float* qb = g_qkv + (size_t)(0 * BB + b) * GG * DD;
    const float* kb = g_qkv + (size_t)(1 * BB + b) * GG * DD;
    const float* vb = g_qkv + (size_t)(2 * BB + b) * GG * DD;

#pragma unroll
    for (int k = 0; k < 32; ++k) {
        int f = tid + 128 * k;
        int row = f >> 4, c4 = f & 15;
        *(float4*)&ksm[row * LDSF + 4 * c4] = ((const float4*)(kb + row * 64))[c4];
        *(float4*)&vsm[row * LDSF + 4 * c4] = ((const float4*)(vb + row * 64))[c4];
    }
    __syncthreads();

    const int warp = tid >> 5, lane = tid & 31;

    for (int t0 = 0; t0 < 16; ++t0) {
        const int n = chunk * 16 + t0;
        if (tid < 64) sq[tid] = qb[n * 64 + tid];
        __syncthreads();

        const int hq = warp * 16;
        float4 q0 = *(const float4*)&sq[hq];
        float4 q1 = *(const float4*)&sq[hq + 4];
        float4 q2 = *(const float4*)&sq[hq + 8];
        float4 q3 = *(const float4*)&sq[hq + 12];
        float vals[8];
#pragma unroll
        for (int k = 0; k < 8; ++k) {
            int m = lane + 32 * k;
            const float* kr = ksm + m * LDSF + hq;
            float4 k0 = *(const float4*)kr;
            float4 k1 = *(const float4*)(kr + 4);
            float4 k2 = *(const float4*)(kr + 8);
            float4 k3 = *(const float4*)(kr + 12);
            float s = q0.x * k0.x + q0.y * k0.y + q0.z * k0.z + q0.w * k0.w
                    + q1.x * k1.x + q1.y * k1.y + q1.z * k1.z + q1.w * k1.w
                    + q2.x * k2.x + q2.y * k2.y + q2.z * k2.z + q2.w * k2.w
                    + q3.x * k3.x + q3.y * k3.y + q3.z * k3.z + q3.w * k3.w;
            vals[k] = 4.0f * s;
        }
        float mx = vals[0];
#pragma unroll
        for (int k = 1; k < 8; ++k) mx = fmaxf(mx, vals[k]);
#pragma unroll
        for (int off = 16; off; off >>= 1) mx = fmaxf(mx, __shfl_xor_sync(0xffffffffu, mx, off));
        float sum = 0.f;
#pragma unroll
        for (int k = 0; k < 8; ++k) { vals[k] = __expf(vals[k] - mx); sum += vals[k]; }
#pragma unroll
        for (int off = 16; off; off >>= 1) sum += __shfl_xor_sync(0xffffffffu, sum, off);
        float inv = 1.f / sum;
#pragma unroll
        for (int k = 0; k < 8; ++k) ss[warp * 264 + lane + 32 * k] = vals[k] * inv;
        __syncthreads();

        if (tid < 64) {
            const int h = tid >> 4, dd = tid & 15;
            const float* pr = ss + h * 264;
            const float* vr = vsm + h * 16 + dd;
            float acc = 0.f;
#pragma unroll 8
            for (int m = 0; m < 256; ++m) acc = fmaf(pr[m], vr[m * LDSF], acc);
            so[tid] = acc;
        }
        __syncthreads();

        if (tid < 64) {
            const float* wr = Wo + tid * 64;
            float acc = bo[tid];
#pragma unroll 8
            for (int d = 0; d < 64; ++d) acc = fmaf(so[d], wr[d], acc);
            g_inter[((size_t)b * GG + n) * DD + tid] = acc;
        }
        __syncthreads();
    }
}

// ---------------- Kernel 4: broadcast-add inter, scattered ----------------
__global__ __launch_bounds__(256) void add_scatter_kernel(
    const int* __restrict__ part, float* __restrict__ out)
{
    __shared__ __align__(16) float iv[64];
    __shared__ int toks[64];
    const int tid = threadIdx.x;
    const int b = blockIdx.x >> 8;
    const int g = blockIdx.x & 255;
    if (tid < 64) iv[tid] = g_inter[((size_t)b * GG + g) * DD + tid];
    else if (tid < 128) toks[tid - 64] = part[(size_t)g * CC + (tid - 64)];
    __syncthreads();
#pragma unroll
    for (int k = 0; k < 4; ++k) {
        int f = tid + 256 * k;
        int row = f >> 4, c4 = f & 15;
        float* p = out + ((size_t)b * NTOK + toks[row]) * DD + 4 * c4;
        float4 v = *(float4*)p;
        float4 a = *(const float4*)&iv[4 * c4];
        v.x += a.x; v.y += a.y; v.z += a.z; v.w += a.w;
        *(float4*)p = v;
    }
}

// ---------------- launch ----------------
extern "C" void kernel_launch(void* const* d_in, const int* in_sizes, int n_in,
                              void* d_out, int out_size)
{
    (void)in_sizes; (void)n_in; (void)out_size;
    const float* x    = (const float*)d_in[0];
    const int*   part = (const int*)d_in[1];   // int32 on device (JAX x64 disabled)
    const float* Wq_a = (const float*)d_in[2];
    const float* bq_a = (const float*)d_in[3];
    const float* Wk_a = (const float*)d_in[4];
    const float* bk_a = (const float*)d_in[5];
    const float* Wv_a = (const float*)d_in[6];
    const float* bv_a = (const float*)d_in[7];
    const float* Wo_a = (const float*)d_in[8];
    const float* bo_a = (const float*)d_in[9];
    const float* Wq_i = (const float*)d_in[10];
    const float* bq_i = (const float*)d_in[11];
    const float* Wk_i = (const float*)d_in[12];
    const float* bk_i = (const float*)d_in[13];
    const float* Wv_i = (const float*)d_in[14];
    const float* bv_i = (const float*)d_in[15];
    const float* Wo_i = (const float*)d_in[16];
    const float* bo_i = (const float*)d_in[17];
    float* out = (float*)d_out;

    const int smem_intra = 6 * 64 * LDSF * (int)sizeof(float);                 // 104448 B
    const int smem_iatt  = (2 * 256 * LDSF + 4 * 264 + 128) * (int)sizeof(float); // 144000 B
    cudaFuncSetAttribute(intra_kernel, cudaFuncAttributeMaxDynamicSharedMemorySize, smem_intra);
    cudaFuncSetAttribute(inter_attn_kernel, cudaFuncAttributeMaxDynamicSharedMemorySize, smem_iatt);

    intra_kernel<<<BB * GG, 512, smem_intra>>>(x, part,
        Wq_a, bq_a, Wk_a, bk_a, Wv_a, bv_a, Wo_a, bo_a, out);
    inter_qkv_kernel<<<192, 256>>>(Wq_i, bq_i, Wk_i, bk_i, Wv_i, bv_i);
    inter_attn_kernel<<<256, 128, smem_iatt>>>(Wo_i, bo_i);
    add_scatter_kernel<<<BB * GG, 256>>>(part, out);
}

// round 7
// speedup vs baseline: 1.4727x; 1.4727x over previous
#include <cuda_runtime.h>
#include <cuda_fp16.h>
#include <cstdint>

// Problem constants (fixed by the dataset)
constexpr int BB   = 16;     // batch
constexpr int NTOK = 16384;  // tokens
constexpr int DD   = 64;     // model dim (= dhf)
constexpr int GG   = 256;    // groups
constexpr int CC   = 64;     // tokens per group
constexpr int NH   = 4;      // heads
// SCALE = 4.0 multiplies scores; folded into Q at store (exact: power of two)

#define PADH 72   // half-precision smem row stride (144 B, ldmatrix conflict-free)
#define LDSF 68   // fp32 smem row stride (inter path + score buffer)

// smem layout (half indices)
#define XH_OFF 0
#define QH_OFF 4608
#define KH_OFF 9216
#define VH_OFF 13824
#define WA_OFF 18432
#define WB_OFF 23040
#define PB_OFF 18432            // probs overlay on WA (Wv dead by then)
#define SBUF_HOFF 27648         // fp32 score buffer starts here (byte 55296)
#define SMEM_INTRA_BYTES (27648 * 2 + 64 * LDSF * 4)   // 55296 + 17408 = 72704

// ---------------- scratch (no allocations allowed) ----------------
__device__ float g_pooled[BB * GG * DD];      // 1 MiB
__device__ float g_qkv[3 * BB * GG * DD];     // 3 MiB  [q/k/v][b][n][d]
__device__ float g_inter[BB * GG * DD];       // 1 MiB

// ---------------- mma / ldmatrix helpers ----------------
__device__ __forceinline__ void ldsm_x4(uint32_t& r0, uint32_t& r1, uint32_t& r2, uint32_t& r3, uint32_t a) {
    asm volatile("ldmatrix.sync.aligned.m8n8.x4.shared.b16 {%0,%1,%2,%3}, [%4];"
        : "=r"(r0), "=r"(r1), "=r"(r2), "=r"(r3) : "r"(a));
}
__device__ __forceinline__ void ldsm_x2(uint32_t& r0, uint32_t& r1, uint32_t a) {
    asm volatile("ldmatrix.sync.aligned.m8n8.x2.shared.b16 {%0,%1}, [%2];"
        : "=r"(r0), "=r"(r1) : "r"(a));
}
__device__ __forceinline__ void ldsm_x2t(uint32_t& r0, uint32_t& r1, uint32_t a) {
    asm volatile("ldmatrix.sync.aligned.m8n8.x2.trans.shared.b16 {%0,%1}, [%2];"
        : "=r"(r0), "=r"(r1) : "r"(a));
}
__device__ __forceinline__ void mma16(float c[4],
    uint32_t a0, uint32_t a1, uint32_t a2, uint32_t a3, uint32_t b0, uint32_t b1) {
    asm volatile("mma.sync.aligned.m16n8k16.row.col.f32.f16.f16.f32 "
        "{%0,%1,%2,%3}, {%4,%5,%6,%7}, {%8,%9}, {%0,%1,%2,%3};"
        : "+f"(c[0]), "+f"(c[1]), "+f"(c[2]), "+f"(c[3])
        : "r"(a0), "r"(a1), "r"(a2), "r"(a3), "r"(b0), "r"(b1));
}

// stage 64x64 fp32 row-major matrix into half smem (PADH stride); 256 threads
__device__ __forceinline__ void stageW(const float* __restrict__ W, __half* dst, int tid) {
#pragma unroll
    for (int k = 0; k < 4; ++k) {
        int f = tid + 256 * k;          // float4 index 0..1023
        int row = f >> 4, c4 = f & 15;
        float4 v = ((const float4*)(W + row * 64))[c4];
        __half* d = dst + row * PADH + 4 * c4;
        *(half2*)(d)     = __floats2half2_rn(v.x, v.y);
        *(half2*)(d + 2) = __floats2half2_rn(v.z, v.w);
    }
}

// ---------------- Kernel 1: intra-group MHA (fp16 mma + ldmatrix) ----------------
// grid = 4096 (b*256+g), 256 threads = 8 warps, dyn smem = 72704 B -> 3 blocks/SM
__global__ __launch_bounds__(256, 3) void intra_kernel(
    const float* __restrict__ x, const int* __restrict__ part,
    const float* __restrict__ Wq, const float* __restrict__ bq,
    const float* __restrict__ Wk, const float* __restrict__ bk,
    const float* __restrict__ Wv, const float* __restrict__ bv,
    const float* __restrict__ Wo, const float* __restrict__ bo,
    float* __restrict__ out)
{
    extern __shared__ __half hsm[];
    float* sbuf = (float*)(hsm + SBUF_HOFF);   // 64 x LDSF fp32

    const int tid = threadIdx.x;
    const int bb = blockIdx.x >> 8;
    const int g  = blockIdx.x & 255;
    const int* pg = part + (size_t)g * CC;
    const float* xb = x + (size_t)bb * NTOK * DD;

    const int lane = tid & 31, w = tid >> 5;
    const int mt = w & 3, nq = w >> 2;      // warp tile: rows 16*mt; col-half 32*nq (or 8*nq for AV)
    const int r  = lane >> 2, cc = lane & 3;
    const int ln = lane & 7, sel = lane >> 3;
    // ldmatrix per-lane offsets (in halves)
    const int offA   = (ln + 8 * (sel & 1)) * PADH + 8 * (sel >> 1);  // A [m][k] x4
    const int offB4  = ln * PADH + 8 * sel;                           // B [n][k] x4 (k..k+31)
    const int offB2  = ln * PADH + 8 * (sel & 1);                     // B [n][k] x2 (k..k+15)
    const int offB2t = (lane & 15) * PADH;                            // B [k][n] x2.trans

    const uint32_t sbase = (uint32_t)__cvta_generic_to_shared(hsm);

    // ---- gather x (fp32 -> half) + stage Wq ----
#pragma unroll
    for (int k = 0; k < 4; ++k) {
        int f = tid + 256 * k;
        int row = f >> 4, c4 = f & 15;
        int tok = pg[row];
        float4 v = ((const float4*)(xb + (size_t)tok * DD))[c4];
        __half* d = hsm + XH_OFF + row * PADH + 4 * c4;
        *(half2*)(d)     = __floats2half2_rn(v.x, v.y);
        *(half2*)(d + 2) = __floats2half2_rn(v.z, v.w);
    }
    stageW(Wq, hsm + WA_OFF, tid);
    __syncthreads();

    // ---- projection: D(half) = A(half)@W^T + bias, times scl ----
    auto projH = [&](int Aoff, int Woff, const float* __restrict__ bias, int Doff, float scl) {
        float acc[4][4] = {};
#pragma unroll
        for (int ktp = 0; ktp < 2; ++ktp) {
            const int k0 = 32 * ktp;
            uint32_t aA0, aA1, aA2, aA3, aB0, aB1, aB2, aB3;
            ldsm_x4(aA0, aA1, aA2, aA3, sbase + 2 * (Aoff + 16 * mt * PADH + k0 + offA));
            ldsm_x4(aB0, aB1, aB2, aB3, sbase + 2 * (Aoff + 16 * mt * PADH + k0 + 16 + offA));
#pragma unroll
            for (int nt = 0; nt < 4; ++nt) {
                const int n0 = 32 * nq + 8 * nt;
                uint32_t b0, b1, b2, b3;
                ldsm_x4(b0, b1, b2, b3, sbase + 2 * (Woff + n0 * PADH + k0 + offB4));
                mma16(acc[nt], aA0, aA1, aA2, aA3, b0, b1);
                mma16(acc[nt], aB0, aB1, aB2, aB3, b2, b3);
            }
        }
        const int row0 = 16 * mt + r;
#pragma unroll
        for (int nt = 0; nt < 4; ++nt) {
            const int n0 = 32 * nq + 8 * nt;
            float b0v = bias[n0 + 2 * cc], b1v = bias[n0 + 2 * cc + 1];
            *(half2*)(hsm + Doff + row0 * PADH + n0 + 2 * cc) =
                __floats2half2_rn((acc[nt][0] + b0v) * scl, (acc[nt][1] + b1v) * scl);
            *(half2*)(hsm + Doff + (row0 + 8) * PADH + n0 + 2 * cc) =
                __floats2half2_rn((acc[nt][2] + b0v) * scl, (acc[nt][3] + b1v) * scl);
        }
    };

    projH(XH_OFF, WA_OFF, bq, QH_OFF, 4.0f);  stageW(Wk, hsm + WB_OFF, tid); __syncthreads();
    projH(XH_OFF, WB_OFF, bk, KH_OFF, 1.0f);  stageW(Wv, hsm + WA_OFF, tid); __syncthreads();
    projH(XH_OFF, WA_OFF, bv, VH_OFF, 1.0f);  stageW(Wo, hsm + WB_OFF, tid); __syncthreads();

    // ---- attention ----
    auto scores = [&](int h) {
        const int hq = 16 * h;
        uint32_t a0, a1, a2, a3;
        ldsm_x4(a0, a1, a2, a3, sbase + 2 * (QH_OFF + 16 * mt * PADH + hq + offA));
        const int row0 = 16 * mt + r;
#pragma unroll
        for (int nt = 0; nt < 4; ++nt) {
            const int n0 = 32 * nq + 8 * nt;
            uint32_t b0, b1;
            ldsm_x2(b0, b1, sbase + 2 * (KH_OFF + n0 * PADH + hq + offB2));
            float acc[4] = {};
            mma16(acc, a0, a1, a2, a3, b0, b1);
            sbuf[row0 * LDSF + n0 + 2 * cc]           = acc[0];
            sbuf[row0 * LDSF + n0 + 2 * cc + 1]       = acc[1];
            sbuf[(row0 + 8) * LDSF + n0 + 2 * cc]     = acc[2];
            sbuf[(row0 + 8) * LDSF + n0 + 2 * cc + 1] = acc[3];
        }
    };
    auto softmax_ph = [&]() {
        const int row = tid >> 2, seg = tid & 3;
        const float* rr = sbuf + row * LDSF + seg * 16;
        float mx = rr[0];
#pragma unroll
        for (int m = 1; m < 16; ++m) mx = fmaxf(mx, rr[m]);
        mx = fmaxf(mx, __shfl_xor_sync(0xffffffffu, mx, 1));
        mx = fmaxf(mx, __shfl_xor_sync(0xffffffffu, mx, 2));
        float e[16];
        float sum = 0.f;
#pragma unroll
        for (int m = 0; m < 16; ++m) { e[m] = __expf(rr[m] - mx); sum += e[m]; }
        sum += __shfl_xor_sync(0xffffffffu, sum, 1);
        sum += __shfl_xor_sync(0xffffffffu, sum, 2);
        float inv = 1.f / sum;
        __half* pd = hsm + PB_OFF + row * PADH + seg * 16;
#pragma unroll
        for (int m = 0; m < 16; m += 2)
            *(half2*)(pd + m) = __floats2half2_rn(e[m] * inv, e[m + 1] * inv);
    };
    auto av = [&](int h) {
        const int hq = 16 * h;
        const int nbase = hq + 8 * nq;   // warp covers 8 of this head's 16 cols
        float oacc[4] = {};
#pragma unroll
        for (int kt = 0; kt < 4; ++kt) {
            const int k0 = 16 * kt;
            uint32_t a0, a1, a2, a3, b0, b1;
            ldsm_x4(a0, a1, a2, a3, sbase + 2 * (PB_OFF + 16 * mt * PADH + k0 + offA));
            ldsm_x2t(b0, b1, sbase + 2 * (VH_OFF + k0 * PADH + nbase + offB2t));
            mma16(oacc, a0, a1, a2, a3, b0, b1);
        }
        const int row0 = 16 * mt + r;
        *(half2*)(hsm + XH_OFF + row0 * PADH + nbase + 2 * cc) =
            __floats2half2_rn(oacc[0], oacc[1]);
        *(half2*)(hsm + XH_OFF + (row0 + 8) * PADH + nbase + 2 * cc) =
            __floats2half2_rn(oacc[2], oacc[3]);
    };

    scores(0); __syncthreads();
#pragma unroll 1
    for (int h = 0; h < NH; ++h) {
        softmax_ph(); __syncthreads();
        av(h);
        if (h < NH - 1) scores(h + 1);
        __syncthreads();
    }

    // ---- O projection (+bias) -> gmem scatter + fp32 stash -> pooled max ----
    {
        float acc[4][4] = {};
#pragma unroll
        for (int ktp = 0; ktp < 2; ++ktp) {
            const int k0 = 32 * ktp;
            uint32_t aA0, aA1, aA2, aA3, aB0, aB1, aB2, aB3;
            ldsm_x4(aA0, aA1, aA2, aA3, sbase + 2 * (XH_OFF + 16 * mt * PADH + k0 + offA));
            ldsm_x4(aB0, aB1, aB2, aB3, sbase + 2 * (XH_OFF + 16 * mt * PADH + k0 + 16 + offA));
#pragma unroll
            for (int nt = 0; nt < 4; ++nt) {
                const int n0 = 32 * nq + 8 * nt;
                uint32_t b0, b1, b2, b3;
                ldsm_x4(b0, b1, b2, b3, sbase + 2 * (WB_OFF + n0 * PADH + k0 + offB4));
                mma16(acc[nt], aA0, aA1, aA2, aA3, b0, b1);
                mma16(acc[nt], aB0, aB1, aB2, aB3, b2, b3);
            }
        }
        const int row0 = 16 * mt + r;
        const int tokA = pg[row0], tokB = pg[row0 + 8];
        float* oA = out + ((size_t)bb * NTOK + tokA) * DD;
        float* oB = out + ((size_t)bb * NTOK + tokB) * DD;
#pragma unroll
        for (int nt = 0; nt < 4; ++nt) {
            const int n0 = 32 * nq + 8 * nt;
            float b0v = bo[n0 + 2 * cc], b1v = bo[n0 + 2 * cc + 1];
            float v0 = acc[nt][0] + b0v, v1 = acc[nt][1] + b1v;
            float v2 = acc[nt][2] + b0v, v3 = acc[nt][3] + b1v;
            *(float2*)(oA + n0 + 2 * cc) = make_float2(v0, v1);
            *(float2*)(oB + n0 + 2 * cc) = make_float2(v2, v3);
            *(float2*)&sbuf[row0 * LDSF + n0 + 2 * cc]       = make_float2(v0, v1);
            *(float2*)&sbuf[(row0 + 8) * LDSF + n0 + 2 * cc] = make_float2(v2, v3);
        }
    }
    __syncthreads();
    if (tid < 64) {
        float m = sbuf[tid];
#pragma unroll 8
        for (int n = 1; n < 64; ++n) m = fmaxf(m, sbuf[n * LDSF + tid]);
        g_pooled[((size_t)bb * GG + g) * DD + tid] = m;
    }
}

// ---------------- helpers for fp32 inter path ----------------
__device__ __forceinline__ void fma16f(float acc[4][4], const float4 a[4], const float4 w[4]) {
#pragma unroll
    for (int i = 0; i < 4; ++i)
#pragma unroll
        for (int j = 0; j < 4; ++j) {
            acc[i][j] = fmaf(a[i].x, w[j].x, acc[i][j]);
            acc[i][j] = fmaf(a[i].y, w[j].y, acc[i][j]);
            acc[i][j] = fmaf(a[i].z, w[j].z, acc[i][j]);
            acc[i][j] = fmaf(a[i].w, w[j].w, acc[i][j]);
        }
}

// ---------------- Kernel 2: inter QKV projections ----------------
__global__ __launch_bounds__(256) void inter_qkv_kernel(
    const float* __restrict__ Wq, const float* __restrict__ bq,
    const float* __restrict__ Wk, const float* __restrict__ bk,
    const float* __restrict__ Wv, const float* __restrict__ bv)
{
    __shared__ float As[64 * LDSF];
    __shared__ float ws[64 * LDSF];
    const int tid = threadIdx.x;
    const int blk = blockIdx.x;
    const int wsel = blk >> 6;
    const int b = (blk >> 2) & 15;
    const int quarter = blk & 3;
    const float* W = (wsel == 0) ? Wq : ((wsel == 1) ? Wk : Wv);
    const float* bias = (wsel == 0) ? bq : ((wsel == 1) ? bk : bv);
    const float* A = g_pooled + ((size_t)b * GG + quarter * 64) * DD;
    float* dst = g_qkv + ((size_t)(wsel * BB + b) * GG + quarter * 64) * DD;

#pragma unroll
    for (int k = 0; k < 4; ++k) {
        int f = tid + 256 * k;
        int r = f >> 4, c4 = f & 15;
        *(float4*)&As[r * LDSF + 4 * c4] = ((const float4*)(A + r * 64))[c4];
        *(float4*)&ws[r * LDSF + 4 * c4] = ((const float4*)(W + r * 64))[c4];
    }
    __syncthreads();

    const int tn = tid >> 4, to = tid & 15;
    float acc[4][4] = {};
#pragma unroll 4
    for (int d4 = 0; d4 < 64; d4 += 4) {
        float4 a[4], w[4];
#pragma unroll
        for (int i = 0; i < 4; ++i) a[i] = *(const float4*)&As[(4 * tn + i) * LDSF + d4];
#pragma unroll
        for (int j = 0; j < 4; ++j) w[j] = *(const float4*)&ws[(4 * to + j) * LDSF + d4];
        fma16f(acc, a, w);
    }
    float bj[4];
#pragma unroll
    for (int j = 0; j < 4; ++j) bj[j] = bias[4 * to + j];
#pragma unroll
    for (int i = 0; i < 4; ++i) {
        float4 v;
        v.x = acc[i][0] + bj[0];
        v.y = acc[i][1] + bj[1];
        v.z = acc[i][2] + bj[2];
        v.w = acc[i][3] + bj[3];
        *(float4*)&dst[(4 * tn + i) * 64 + 4 * to] = v;
    }
}

// ---------------- Kernel 3: inter attention (+ O proj) ----------------
__global__ __launch_bounds__(128) void inter_attn_kernel(
    const float* __restrict__ Wo, const float* __restrict__ bo)
{
    extern __shared__ float sm2[];
    float* ksm = sm2;
    float* vsm = sm2 + 256 * LDSF;
    float* ss  = sm2 + 2 * 256 * LDSF;  // 4 * 264
    float* sq  = ss + 4 * 264;          // 64
    float* so  = sq + 64;               // 64

    const int tid = threadIdx.x;
    const int b = blockIdx.x >> 4;
    const int chunk = blockIdx.x & 15;

    const float* qb = g_qkv + (size_t)(0 * BB + b) * GG * DD;
    const float* kb = g_qkv + (size_t)(1 * BB + b) * GG * DD;
    const float* vb = g_qkv + (size_t)(2 * BB + b) * GG * DD;

#pragma unroll
    for (int k = 0; k < 32; ++k) {
        int f = tid + 128 * k;
        int row = f >> 4, c4 = f & 15;
        *(float4*)&ksm[row * LDSF + 4 * c4] = ((const float4*)(kb + row * 64))[c4];
        *(float4*)&vsm[row * LDSF + 4 * c4] = ((const float4*)(vb + row * 64))[c4];
    }
    __syncthreads();

    const int warp = tid >> 5, lane = tid & 31;

    for (int t0 = 0; t0 < 16; ++t0) {
        const int n = chunk * 16 + t0;
        if (tid < 64) sq[tid] = qb[n * 64 + tid];
        __syncthreads();

        const int hq = warp * 16;
        float4 q0 = *(const float4*)&sq[hq];
        float4 q1 = *(const float4*)&sq[hq + 4];
        float4 q2 = *(const float4*)&sq[hq + 8];
        float4 q3 = *(const float4*)&sq[hq + 12];
        float vals[8];
#pragma unroll
        for (int k = 0; k < 8; ++k) {
            int m = lane + 32 * k;
            const float* kr = ksm + m * LDSF + hq;
            float4 k0 = *(const float4*)kr;
            float4 k1 = *(const float4*)(kr + 4);
            float4 k2 = *(const float4*)(kr + 8);
            float4 k3 = *(const float4*)(kr + 12);
            float s = q0.x * k0.x + q0.y * k0.y + q0.z * k0.z + q0.w * k0.w
                    + q1.x * k1.x + q1.y * k1.y + q1.z * k1.z + q1.w * k1.w
                    + q2.x * k2.x + q2.y * k2.y + q2.z * k2.z + q2.w * k2.w
                    + q3.x * k3.x + q3.y * k3.y + q3.z * k3.z + q3.w * k3.w;
            vals[k] = 4.0f * s;
        }
        float mx = vals[0];
#pragma unroll
        for (int k = 1; k < 8; ++k) mx = fmaxf(mx, vals[k]);
#pragma unroll
        for (int off = 16; off; off >>= 1) mx = fmaxf(mx, __shfl_xor_sync(0xffffffffu, mx, off));
        float sum = 0.f;
#pragma unroll
        for (int k = 0; k < 8; ++k) { vals[k] = __expf(vals[k] - mx); sum += vals[k]; }
#pragma unroll
        for (int off = 16; off; off >>= 1) sum += __shfl_xor_sync(0xffffffffu, sum, off);
        float inv = 1.f / sum;
#pragma unroll
        for (int k = 0; k < 8; ++k) ss[warp * 264 + lane + 32 * k] = vals[k] * inv;
        __syncthreads();

        if (tid < 64) {
            const int h = tid >> 4, dd = tid & 15;
            const float* pr = ss + h * 264;
            const float* vr = vsm + h * 16 + dd;
            float acc = 0.f;
#pragma unroll 8
            for (int m = 0; m < 256; ++m) acc = fmaf(pr[m], vr[m * LDSF], acc);
            so[tid] = acc;
        }
        __syncthreads();

        if (tid < 64) {
            const float* wr = Wo + tid * 64;
            float acc = bo[tid];
#pragma unroll 8
            for (int d = 0; d < 64; ++d) acc = fmaf(so[d], wr[d], acc);
            g_inter[((size_t)b * GG + n) * DD + tid] = acc;
        }
        __syncthreads();
    }
}

// ---------------- Kernel 4: broadcast-add inter, scattered ----------------
__global__ __launch_bounds__(256) void add_scatter_kernel(
    const int* __restrict__ part, float* __restrict__ out)
{
    __shared__ __align__(16) float iv[64];
    __shared__ int toks[64];
    const int tid = threadIdx.x;
    const int b = blockIdx.x >> 8;
    const int g = blockIdx.x & 255;
    if (tid < 64) iv[tid] = g_inter[((size_t)b * GG + g) * DD + tid];
    else if (tid < 128) toks[tid - 64] = part[(size_t)g * CC + (tid - 64)];
    __syncthreads();
#pragma unroll
    for (int k = 0; k < 4; ++k) {
        int f = tid + 256 * k;
        int row = f >> 4, c4 = f & 15;
        float* p = out + ((size_t)b * NTOK + toks[row]) * DD + 4 * c4;
        float4 v = *(float4*)p;
        float4 a = *(const float4*)&iv[4 * c4];
        v.x += a.x; v.y += a.y; v.z += a.z; v.w += a.w;
        *(float4*)p = v;
    }
}

// ---------------- launch ----------------
extern "C" void kernel_launch(void* const* d_in, const int* in_sizes, int n_in,
                              void* d_out, int out_size)
{
    (void)in_sizes; (void)n_in; (void)out_size;
    const float* x    = (const float*)d_in[0];
    const int*   part = (const int*)d_in[1];   // int32 on device (JAX x64 disabled)
    const float* Wq_a = (const float*)d_in[2];
    const float* bq_a = (const float*)d_in[3];
    const float* Wk_a = (const float*)d_in[4];
    const float* bk_a = (const float*)d_in[5];
    const float* Wv_a = (const float*)d_in[6];
    const float* bv_a = (const float*)d_in[7];
    const float* Wo_a = (const float*)d_in[8];
    const float* bo_a = (const float*)d_in[9];
    const float* Wq_i = (const float*)d_in[10];
    const float* bq_i = (const float*)d_in[11];
    const float* Wk_i = (const float*)d_in[12];
    const float* bk_i = (const float*)d_in[13];
    const float* Wv_i = (const float*)d_in[14];
    const float* bv_i = (const float*)d_in[15];
    const float* Wo_i = (const float*)d_in[16];
    const float* bo_i = (const float*)d_in[17];
    float* out = (float*)d_out;

    const int smem_intra = SMEM_INTRA_BYTES;                                      // 72704 B
    const int smem_iatt  = (2 * 256 * LDSF + 4 * 264 + 128) * (int)sizeof(float); // 144000 B
    cudaFuncSetAttribute(intra_kernel, cudaFuncAttributeMaxDynamicSharedMemorySize, smem_intra);
    cudaFuncSetAttribute(inter_attn_kernel, cudaFuncAttributeMaxDynamicSharedMemorySize, smem_iatt);

    intra_kernel<<<BB * GG, 256, smem_intra>>>(x, part,
        Wq_a, bq_a, Wk_a, bk_a, Wv_a, bv_a, Wo_a, bo_a, out);
    inter_qkv_kernel<<<192, 256>>>(Wq_i, bq_i, Wk_i, bk_i, Wv_i, bv_i);
    inter_attn_kernel<<<256, 128, smem_iatt>>>(Wo_i, bo_i);
    add_scatter_kernel<<<BB * GG, 256>>>(part, out);
}

// round 9
// speedup vs baseline: 1.7569x; 1.1929x over previous
#include <cuda_runtime.h>
#include <cuda_fp16.h>
#include <cstdint>

// Problem constants (fixed by the dataset)
constexpr int BB   = 16;     // batch
constexpr int NTOK = 16384;  // tokens
constexpr int DD   = 64;     // model dim (= dhf)
constexpr int GG   = 256;    // groups
constexpr int CC   = 64;     // tokens per group
constexpr int NH   = 4;      // heads
// SCALE = 4.0 multiplies scores; folded into Q at store (exact: power of two)

#define PADH 72   // half-precision smem row stride (144 B, ldmatrix conflict-free)
#define LDSF 68   // fp32 smem row stride (inter path + pooled-max stash)

// smem layout (half indices)
#define XH_OFF 0
#define QH_OFF 4608
#define KH_OFF 9216
#define VH_OFF 13824
#define WA_OFF 18432
#define WB_OFF 23040
#define SMEM_INTRA_BYTES (27648 * 2)   // 55296 B -> 3-4 blocks/SM
// pooled-max fp32 stash overlays dead Q/K buffers (bytes 9216..26624)

// ---------------- scratch (no allocations allowed) ----------------
__device__ float g_pooled[BB * GG * DD];      // 1 MiB
__device__ float g_qkv[3 * BB * GG * DD];     // 3 MiB  [q/k/v][b][n][d]
__device__ float g_inter[BB * GG * DD];      // 1 MiB

// ---------------- mma / ldmatrix helpers ----------------
__device__ __forceinline__ void ldsm_x4(uint32_t& r0, uint32_t& r1, uint32_t& r2, uint32_t& r3, uint32_t a) {
    asm volatile("ldmatrix.sync.aligned.m8n8.x4.shared.b16 {%0,%1,%2,%3}, [%4];"
        : "=r"(r0), "=r"(r1), "=r"(r2), "=r"(r3) : "r"(a));
}
__device__ __forceinline__ void ldsm_x2(uint32_t& r0, uint32_t& r1, uint32_t a) {
    asm volatile("ldmatrix.sync.aligned.m8n8.x2.shared.b16 {%0,%1}, [%2];"
        : "=r"(r0), "=r"(r1) : "r"(a));
}
__device__ __forceinline__ void ldsm_x2t(uint32_t& r0, uint32_t& r1, uint32_t a) {
    asm volatile("ldmatrix.sync.aligned.m8n8.x2.trans.shared.b16 {%0,%1}, [%2];"
        : "=r"(r0), "=r"(r1) : "r"(a));
}
__device__ __forceinline__ void mma16(float c[4],
    uint32_t a0, uint32_t a1, uint32_t a2, uint32_t a3, uint32_t b0, uint32_t b1) {
    asm volatile("mma.sync.aligned.m16n8k16.row.col.f32.f16.f16.f32 "
        "{%0,%1,%2,%3}, {%4,%5,%6,%7}, {%8,%9}, {%0,%1,%2,%3};"
        : "+f"(c[0]), "+f"(c[1]), "+f"(c[2]), "+f"(c[3])
        : "r"(a0), "r"(a1), "r"(a2), "r"(a3), "r"(b0), "r"(b1));
}
// pack two fp32 into one fp16x2 register (round-to-nearest-even)
__device__ __forceinline__ uint32_t packh2(float a, float b) {
    uint32_t u;
    asm("cvt.rn.f16x2.f32 %0, %1, %2;" : "=r"(u) : "f"(b), "f"(a));
    return u;
}

// stage 64x64 fp32 row-major matrix into half smem (PADH stride); 256 threads
__device__ __forceinline__ void stageW(const float* __restrict__ W, __half* dst, int tid) {
#pragma unroll
    for (int k = 0; k < 4; ++k) {
        int f = tid + 256 * k;          // float4 index 0..1023
        int row = f >> 4, c4 = f & 15;
        float4 v = ((const float4*)(W + row * 64))[c4];
        __half* d = dst + row * PADH + 4 * c4;
        *(half2*)(d)     = __floats2half2_rn(v.x, v.y);
        *(half2*)(d + 2) = __floats2half2_rn(v.z, v.w);
    }
}

// ---------------- Kernel 1: intra-group MHA (fp16 mma, register attention) ----------------
// grid = 4096 (b*256+g), 256 threads = 8 warps, dyn smem = 55296 B
__global__ __launch_bounds__(256, 3) void intra_kernel(
    const float* __restrict__ x, const int* __restrict__ part,
    const float* __restrict__ Wq, const float* __restrict__ bq,
    const float* __restrict__ Wk, const float* __restrict__ bk,
    const float* __restrict__ Wv, const float* __restrict__ bv,
    const float* __restrict__ Wo, const float* __restrict__ bo,
    float* __restrict__ out)
{
    extern __shared__ __half hsm[];
    float* stash = (float*)(hsm + QH_OFF);   // 64 x LDSF fp32 overlay (dead Q/K)

    const int tid = threadIdx.x;
    const int bb = blockIdx.x >> 8;
    const int g  = blockIdx.x & 255;
    const int* pg = part + (size_t)g * CC;
    const float* xb = x + (size_t)bb * NTOK * DD;

    const int lane = tid & 31, w = tid >> 5;
    const int mt = w & 3, nq = w >> 2;      // projection tiling: rows 16*mt, cols 32*nq
    const int r  = lane >> 2, cc = lane & 3;
    const int ln = lane & 7, sel = lane >> 3;
    // ldmatrix per-lane offsets (in halves)
    const int offA   = (ln + 8 * (sel & 1)) * PADH + 8 * (sel >> 1);  // A [m][k] x4
    const int offB4  = ln * PADH + 8 * sel;                           // B [n][k] x4
    const int offB2  = ln * PADH + 8 * (sel & 1);                     // B [n][k] x2
    const int offB2t = (lane & 15) * PADH;                            // B [k][n] x2.trans

    const uint32_t sbase = (uint32_t)__cvta_generic_to_shared(hsm);

    // ---- gather x (fp32 -> half) + stage Wq ----
#pragma unroll
    for (int k = 0; k < 4; ++k) {
        int f = tid + 256 * k;
        int row = f >> 4, c4 = f & 15;
        int tok = pg[row];
        float4 v = ((const float4*)(xb + (size_t)tok * DD))[c4];
        __half* d = hsm + XH_OFF + row * PADH + 4 * c4;
        *(half2*)(d)     = __floats2half2_rn(v.x, v.y);
        *(half2*)(d + 2) = __floats2half2_rn(v.z, v.w);
    }
    stageW(Wq, hsm + WA_OFF, tid);
    __syncthreads();

    // ---- projection: D(half) = A(half)@W^T + bias, times scl ----
    auto projH = [&](int Aoff, int Woff, const float* __restrict__ bias, int Doff, float scl) {
        float acc[4][4] = {};
#pragma unroll
        for (int ktp = 0; ktp < 2; ++ktp) {
            const int k0 = 32 * ktp;
            uint32_t aA0, aA1, aA2, aA3, aB0, aB1, aB2, aB3;
            ldsm_x4(aA0, aA1, aA2, aA3, sbase + 2 * (Aoff + 16 * mt * PADH + k0 + offA));
            ldsm_x4(aB0, aB1, aB2, aB3, sbase + 2 * (Aoff + 16 * mt * PADH + k0 + 16 + offA));
#pragma unroll
            for (int nt = 0; nt < 4; ++nt) {
                const int n0 = 32 * nq + 8 * nt;
                uint32_t b0, b1, b2, b3;
                ldsm_x4(b0, b1, b2, b3, sbase + 2 * (Woff + n0 * PADH + k0 + offB4));
                mma16(acc[nt], aA0, aA1, aA2, aA3, b0, b1);
                mma16(acc[nt], aB0, aB1, aB2, aB3, b2, b3);
            }
        }
        const int row0 = 16 * mt + r;
#pragma unroll
        for (int nt = 0; nt < 4; ++nt) {
            const int n0 = 32 * nq + 8 * nt;
            float b0v = bias[n0 + 2 * cc], b1v = bias[n0 + 2 * cc + 1];
            *(half2*)(hsm + Doff + row0 * PADH + n0 + 2 * cc) =
                __floats2half2_rn((acc[nt][0] + b0v) * scl, (acc[nt][1] + b1v) * scl);
            *(half2*)(hsm + Doff + (row0 + 8) * PADH + n0 + 2 * cc) =
                __floats2half2_rn((acc[nt][2] + b0v) * scl, (acc[nt][3] + b1v) * scl);
        }
    };

    projH(XH_OFF, WA_OFF, bq, QH_OFF, 4.0f);  stageW(Wk, hsm + WB_OFF, tid); __syncthreads();
    projH(XH_OFF, WB_OFF, bk, KH_OFF, 1.0f);  stageW(Wv, hsm + WA_OFF, tid); __syncthreads();
    projH(XH_OFF, WA_OFF, bv, VH_OFF, 1.0f);  stageW(Wo, hsm + WB_OFF, tid); __syncthreads();

    // ---- attention, fully register-resident; warp = (row-tile, head-pair lane) ----
    // warp covers rows 16*mt, all 64 key-cols, heads {hsel, 2+hsel}
    {
        const int hsel = w >> 2;
        const int arow = 16 * mt;   // same mt as projections
#pragma unroll
        for (int hp = 0; hp < 2; ++hp) {
            const int h = 2 * hp + hsel;
            const int hq = 16 * h;
            // scores: S = Qh @ Kh^T (Q pre-scaled by 4)
            uint32_t a0, a1, a2, a3;
            ldsm_x4(a0, a1, a2, a3, sbase + 2 * (QH_OFF + arow * PADH + hq + offA));
            float s[8][4];
#pragma unroll
            for (int nt = 0; nt < 8; ++nt) {
                uint32_t b0, b1;
                ldsm_x2(b0, b1, sbase + 2 * (KH_OFF + 8 * nt * PADH + hq + offB2));
                s[nt][0] = s[nt][1] = s[nt][2] = s[nt][3] = 0.f;
                mma16(s[nt], a0, a1, a2, a3, b0, b1);
            }
            // softmax: row r (elems [0],[1]) and row r+8 ([2],[3]); quad shuffles
            float mx0 = -1e30f, mx1 = -1e30f;
#pragma unroll
            for (int nt = 0; nt < 8; ++nt) {
                mx0 = fmaxf(mx0, fmaxf(s[nt][0], s[nt][1]));
                mx1 = fmaxf(mx1, fmaxf(s[nt][2], s[nt][3]));
            }
            mx0 = fmaxf(mx0, __shfl_xor_sync(0xffffffffu, mx0, 1));
            mx0 = fmaxf(mx0, __shfl_xor_sync(0xffffffffu, mx0, 2));
            mx1 = fmaxf(mx1, __shfl_xor_sync(0xffffffffu, mx1, 1));
            mx1 = fmaxf(mx1, __shfl_xor_sync(0xffffffffu, mx1, 2));
            float sum0 = 0.f, sum1 = 0.f;
#pragma unroll
            for (int nt = 0; nt < 8; ++nt) {
                s[nt][0] = __expf(s[nt][0] - mx0); sum0 += s[nt][0];
                s[nt][1] = __expf(s[nt][1] - mx0); sum0 += s[nt][1];
                s[nt][2] = __expf(s[nt][2] - mx1); sum1 += s[nt][2];
                s[nt][3] = __expf(s[nt][3] - mx1); sum1 += s[nt][3];
            }
            sum0 += __shfl_xor_sync(0xffffffffu, sum0, 1);
            sum0 += __shfl_xor_sync(0xffffffffu, sum0, 2);
            sum1 += __shfl_xor_sync(0xffffffffu, sum1, 1);
            sum1 += __shfl_xor_sync(0xffffffffu, sum1, 2);
            const float inv0 = 1.f / sum0, inv1 = 1.f / sum1;
            // AV: P fragments packed directly from score accumulators
            float o[2][4] = {};
#pragma unroll
            for (int kc = 0; kc < 4; ++kc) {
                uint32_t pa0 = packh2(s[2*kc][0] * inv0, s[2*kc][1] * inv0);
                uint32_t pa1 = packh2(s[2*kc][2] * inv1, s[2*kc][3] * inv1);
                uint32_t pa2 = packh2(s[2*kc+1][0] * inv0, s[2*kc+1][1] * inv0);
                uint32_t pa3 = packh2(s[2*kc+1][2] * inv1, s[2*kc+1][3] * inv1);
#pragma unroll
                for (int nt2 = 0; nt2 < 2; ++nt2) {
                    uint32_t b0, b1;
                    ldsm_x2t(b0, b1, sbase + 2 * (VH_OFF + 16 * kc * PADH + hq + 8 * nt2 + offB2t));
                    mma16(o[nt2], pa0, pa1, pa2, pa3, b0, b1);
                }
            }
            // write O_h (rows arow+r/arow+r+8, cols hq+8*nt2+2cc) into xs
#pragma unroll
            for (int nt2 = 0; nt2 < 2; ++nt2) {
                const int n0 = hq + 8 * nt2 + 2 * cc;
                *(half2*)(hsm + XH_OFF + (arow + r) * PADH + n0) =
                    __floats2half2_rn(o[nt2][0], o[nt2][1]);
                *(half2*)(hsm + XH_OFF + (arow + r + 8) * PADH + n0) =
                    __floats2half2_rn(o[nt2][2], o[nt2][3]);
            }
        }
    }
    __syncthreads();

    // ---- O projection (+bias) -> gmem scatter + fp32 stash -> pooled max ----
    {
        float acc[4][4] = {};
#pragma unroll
        for (int ktp = 0; ktp < 2; ++ktp) {
            const int k0 = 32 * ktp;
            uint32_t aA0, aA1, aA2, aA3, aB0, aB1, aB2, aB3;
            ldsm_x4(aA0, aA1, aA2, aA3, sbase + 2 * (XH_OFF + 16 * mt * PADH + k0 + offA));
            ldsm_x4(aB0, aB1, aB2, aB3, sbase + 2 * (XH_OFF + 16 * mt * PADH + k0 + 16 + offA));
#pragma unroll
            for (int nt = 0; nt < 4; ++nt) {
                const int n0 = 32 * nq + 8 * nt;
                uint32_t b0, b1, b2, b3;
                ldsm_x4(b0, b1, b2, b3, sbase + 2 * (WB_OFF + n0 * PADH + k0 + offB4));
                mma16(acc[nt], aA0, aA1, aA2, aA3, b0, b1);
                mma16(acc[nt], aB0, aB1, aB2, aB3, b2, b3);
            }
        }
        const int row0 = 16 * mt + r;
        const int tokA = pg[row0], tokB = pg[row0 + 8];
        float* oA = out + ((size_t)bb * NTOK + tokA) * DD;
        float* oB = out + ((size_t)bb * NTOK + tokB) * DD;
#pragma unroll
        for (int nt = 0; nt < 4; ++nt) {
            const int n0 = 32 * nq + 8 * nt;
            float b0v = bo[n0 + 2 * cc], b1v = bo[n0 + 2 * cc + 1];
            float v0 = acc[nt][0] + b0v, v1 = acc[nt][1] + b1v;
            float v2 = acc[nt][2] + b0v, v3 = acc[nt][3] + b1v;
            *(float2*)(oA + n0 + 2 * cc) = make_float2(v0, v1);
            *(float2*)(oB + n0 + 2 * cc) = make_float2(v2, v3);
            *(float2*)&stash[row0 * LDSF + n0 + 2 * cc]       = make_float2(v0, v1);
            *(float2*)&stash[(row0 + 8) * LDSF + n0 + 2 * cc] = make_float2(v2, v3);
        }
    }
    __syncthreads();
    if (tid < 64) {
        float m = stash[tid];
#pragma unroll 8
        for (int n = 1; n < 64; ++n) m = fmaxf(m, stash[n * LDSF + tid]);
        g_pooled[((size_t)bb * GG + g) * DD + tid] = m;
    }
}

// ---------------- helpers for fp32 inter path ----------------
__device__ __forceinline__ void fma16f(float acc[4][4], const float4 a[4], const float4 w[4]) {
#pragma unroll
    for (int i = 0; i < 4; ++i)
#pragma unroll
        for (int j = 0; j < 4; ++j) {
            acc[i][j] = fmaf(a[i].x, w[j].x, acc[i][j]);
            acc[i][j] = fmaf(a[i].y, w[j].y, acc[i][j]);
            acc[i][j] = fmaf(a[i].z, w[j].z, acc[i][j]);
            acc[i][j] = fmaf(a[i].w, w[j].w, acc[i][j]);
        }
}

// ---------------- Kernel 2: inter QKV projections ----------------
__global__ __launch_bounds__(256) void inter_qkv_kernel(
    const float* __restrict__ Wq, const float* __restrict__ bq,
    const float* __restrict__ Wk, const float* __restrict__ bk,
    const float* __restrict__ Wv, const float* __restrict__ bv)
{
    __shared__ float As[64 * LDSF];
    __shared__ float ws[64 * LDSF];
    const int tid = threadIdx.x;
    const int blk = blockIdx.x;
    const int wsel = blk >> 6;
    const int b = (blk >> 2) & 15;
    const int quarter = blk & 3;
    const float* W = (wsel == 0) ? Wq : ((wsel == 1) ? Wk : Wv);
    const float* bias = (wsel == 0) ? bq : ((wsel == 1) ? bk : bv);
    const float* A = g_pooled + ((size_t)b * GG + quarter * 64) * DD;
    float* dst = g_qkv + ((size_t)(wsel * BB + b) * GG + quarter * 64) * DD;

#pragma unroll
    for (int k = 0; k < 4; ++k) {
        int f = tid + 256 * k;
        int r = f >> 4, c4 = f & 15;
        *(float4*)&As[r * LDSF + 4 * c4] = ((const float4*)(A + r * 64))[c4];
        *(float4*)&ws[r * LDSF + 4 * c4] = ((const float4*)(W + r * 64))[c4];
    }
    __syncthreads();

    const int tn = tid >> 4, to = tid & 15;
    float acc[4][4] = {};
#pragma unroll 4
    for (int d4 = 0; d4 < 64; d4 += 4) {
        float4 a[4], w[4];
#pragma unroll
        for (int i = 0; i < 4; ++i) a[i] = *(const float4*)&As[(4 * tn + i) * LDSF + d4];
#pragma unroll
        for (int j = 0; j < 4; ++j) w[j] = *(const float4*)&ws[(4 * to + j) * LDSF + d4];
        fma16f(acc, a, w);
    }
    float bj[4];
#pragma unroll
    for (int j = 0; j < 4; ++j) bj[j] = bias[4 * to + j];
#pragma unroll
    for (int i = 0; i < 4; ++i) {
        float4 v;
        v.x = acc[i][0] + bj[0];
        v.y = acc[i][1] + bj[1];
        v.z = acc[i][2] + bj[2];
        v.w = acc[i][3] + bj[3];
        *(float4*)&dst[(4 * tn + i) * 64 + 4 * to] = v;
    }
}

// ---------------- Kernel 3: inter attention (+ O proj) ----------------
__global__ __launch_bounds__(128) void inter_attn_kernel(
    const float* __restrict__ Wo, const float* __restrict__ bo)
{
    extern __shared__ float sm2[];
    float* ksm = sm2;
    float* vsm = sm2 + 256 * LDSF;
    float* ss  = sm2 + 2 * 256 * LDSF;  // 4 * 264
    float* sq  = ss + 4 * 264;          // 64
    float* so  = sq + 64;               // 64

    const int tid = threadIdx.x;
    const int b = blockIdx.x >> 4;
    const int chunk = blockIdx.x & 15;

    const float* qb = g_qkv + (size_t)(0 * BB + b) * GG * DD;
    const float* kb = g_qkv + (size_t)(1 * BB + b) * GG * DD;
    const float* vb = g_qkv + (size_t)(2 * BB + b) * GG * DD;

#pragma unroll
    for (int k = 0; k < 32; ++k) {
        int f = tid + 128 * k;
        int row = f >> 4, c4 = f & 15;
        *(float4*)&ksm[row * LDSF + 4 * c4] = ((const float4*)(kb + row * 64))[c4];
        *(float4*)&vsm[row * LDSF + 4 * c4] = ((const float4*)(vb + row * 64))[c4];
    }
    __syncthreads();

    const int warp = tid >> 5, lane = tid & 31;

    for (int t0 = 0; t0 < 16; ++t0) {
        const int n = chunk * 16 + t0;
        if (tid < 64) sq[tid] = qb[n * 64 + tid];
        __syncthreads();

        const int hq = warp * 16;
        float4 q0 = *(const float4*)&sq[hq];
        float4 q1 = *(const float4*)&sq[hq + 4];
        float4 q2 = *(const float4*)&sq[hq + 8];
        float4 q3 = *(const float4*)&sq[hq + 12];
        float vals[8];
#pragma unroll
        for (int k = 0; k < 8; ++k) {
            int m = lane + 32 * k;
            const float* kr = ksm + m * LDSF + hq;
            float4 k0 = *(const float4*)kr;
            float4 k1 = *(const float4*)(kr + 4);
            float4 k2 = *(const float4*)(kr + 8);
            float4 k3 = *(const float4*)(kr + 12);
            float s = q0.x * k0.x + q0.y * k0.y + q0.z * k0.z + q0.w * k0.w
                    + q1.x * k1.x + q1.y * k1.y + q1.z * k1.z + q1.w * k1.w
                    + q2.x * k2.x + q2.y * k2.y + q2.z * k2.z + q2.w * k2.w
                    + q3.x * k3.x + q3.y * k3.y + q3.z * k3.z + q3.w * k3.w;
            vals[k] = 4.0f * s;
        }
        float mx = vals[0];
#pragma unroll
        for (int k = 1; k < 8; ++k) mx = fmaxf(mx, vals[k]);
#pragma unroll
        for (int off = 16; off; off >>= 1) mx = fmaxf(mx, __shfl_xor_sync(0xffffffffu, mx, off));
        float sum = 0.f;
#pragma unroll
        for (int k = 0; k < 8; ++k) { vals[k] = __expf(vals[k] - mx); sum += vals[k]; }
#pragma unroll
        for (int off = 16; off; off >>= 1) sum += __shfl_xor_sync(0xffffffffu, sum, off);
        float inv = 1.f / sum;
#pragma unroll
        for (int k = 0; k < 8; ++k) ss[warp * 264 + lane + 32 * k] = vals[k] * inv;
        __syncthreads();

        if (tid < 64) {
            const int h = tid >> 4, dd = tid & 15;
            const float* pr = ss + h * 264;
            const float* vr = vsm + h * 16 + dd;
            float acc = 0.f;
#pragma unroll 8
            for (int m = 0; m < 256; ++m) acc = fmaf(pr[m], vr[m * LDSF], acc);
            so[tid] = acc;
        }
        __syncthreads();

        if (tid < 64) {
            const float* wr = Wo + tid * 64;
            float acc = bo[tid];
#pragma unroll 8
            for (int d = 0; d < 64; ++d) acc = fmaf(so[d], wr[d], acc);
            g_inter[((size_t)b * GG + n) * DD + tid] = acc;
        }
        __syncthreads();
    }
}

// ---------------- Kernel 4: broadcast-add inter, scattered ----------------
__global__ __launch_bounds__(256) void add_scatter_kernel(
    const int* __restrict__ part, float* __restrict__ out)
{
    __shared__ __align__(16) float iv[64];
    __shared__ int toks[64];
    const int tid = threadIdx.x;
    const int b = blockIdx.x >> 8;
    const int g = blockIdx.x & 255;
    if (tid < 64) iv[tid] = g_inter[((size_t)b * GG + g) * DD + tid];
    else if (tid < 128) toks[tid - 64] = part[(size_t)g * CC + (tid - 64)];
    __syncthreads();
#pragma unroll
    for (int k = 0; k < 4; ++k) {
        int f = tid + 256 * k;
        int row = f >> 4, c4 = f & 15;
        float* p = out + ((size_t)b * NTOK + toks[row]) * DD + 4 * c4;
        float4 v = *(float4*)p;
        float4 a = *(const float4*)&iv[4 * c4];
        v.x += a.x; v.y += a.y; v.z += a.z; v.w += a.w;
        *(float4*)p = v;
    }
}

// ---------------- launch ----------------
extern "C" void kernel_launch(void* const* d_in, const int* in_sizes, int n_in,
                              void* d_out, int out_size)
{
    (void)in_sizes; (void)n_in; (void)out_size;
    const float* x    = (const float*)d_in[0];
    const int*   part = (const int*)d_in[1];   // int32 on device (JAX x64 disabled)
    const float* Wq_a = (const float*)d_in[2];
    const float* bq_a = (const float*)d_in[3];
    const float* Wk_a = (const float*)d_in[4];
    const float* bk_a = (const float*)d_in[5];
    const float* Wv_a = (const float*)d_in[6];
    const float* bv_a = (const float*)d_in[7];
    const float* Wo_a = (const float*)d_in[8];
    const float* bo_a = (const float*)d_in[9];
    const float* Wq_i = (const float*)d_in[10];
    const float* bq_i = (const float*)d_in[11];
    const float* Wk_i = (const float*)d_in[12];
    const float* bk_i = (const float*)d_in[13];
    const float* Wv_i = (const float*)d_in[14];
    const float* bv_i = (const float*)d_in[15];
    const float* Wo_i = (const float*)d_in[16];
    const float* bo_i = (const float*)d_in[17];
    float* out = (float*)d_out;

    const int smem_intra = SMEM_INTRA_BYTES;                                      // 55296 B
    const int smem_iatt  = (2 * 256 * LDSF + 4 * 264 + 128) * (int)sizeof(float); // 144000 B
    cudaFuncSetAttribute(intra_kernel, cudaFuncAttributeMaxDynamicSharedMemorySize, smem_intra);
    cudaFuncSetAttribute(inter_attn_kernel, cudaFuncAttributeMaxDynamicSharedMemorySize, smem_iatt);

    intra_kernel<<<BB * GG, 256, smem_intra>>>(x, part,
        Wq_a, bq_a, Wk_a, bk_a, Wv_a, bv_a, Wo_a, bo_a, out);
    inter_qkv_kernel<<<192, 256>>>(Wq_i, bq_i, Wk_i, bk_i, Wv_i, bv_i);
    inter_attn_kernel<<<256, 128, smem_iatt>>>(Wo_i, bo_i);
    add_scatter_kernel<<<BB * GG, 256>>>(part, out);
}

// round 10
// speedup vs baseline: 1.8062x; 1.0281x over previous
#include <cuda_runtime.h>
#include <cuda_fp16.h>
#include <cstdint>

// Problem constants (fixed by the dataset)
constexpr int BB   = 16;     // batch
constexpr int NTOK = 16384;  // tokens
constexpr int DD   = 64;     // model dim (= dhf)
constexpr int GG   = 256;    // groups
constexpr int CC   = 64;     // tokens per group
constexpr int NH   = 4;      // heads
// SCALE = 4.0 multiplies scores; folded into Q at store (exact: power of two)

#define PADH 72   // half-precision smem row stride (144 B, ldmatrix conflict-free)
#define LDSF 68   // fp32 smem row stride (inter path + pooled-max stash)

// smem layout (half indices)
#define XH_OFF 0
#define QH_OFF 4608
#define KH_OFF 9216
#define VH_OFF 13824
#define SMEM_INTRA_BYTES (4 * 4608 * 2)   // 36864 B
// pooled-max fp32 stash overlays dead Q/K buffers (bytes 9216..26624)

// ---------------- scratch (no allocations allowed) ----------------
__device__ float g_pooled[BB * GG * DD];      // 1 MiB
__device__ float g_qkv[3 * BB * GG * DD];     // 3 MiB  [q/k/v][b][n][d]
__device__ float g_inter[BB * GG * DD];       // 1 MiB
// pre-packed fp16 weight fragments: [mat][ (ntg*4+kt)*64 + 2*lane + j ]
__device__ uint32_t g_wfrag[4][2048];         // 32 KiB

// ---------------- mma / ldmatrix helpers ----------------
__device__ __forceinline__ void ldsm_x4(uint32_t& r0, uint32_t& r1, uint32_t& r2, uint32_t& r3, uint32_t a) {
    asm volatile("ldmatrix.sync.aligned.m8n8.x4.shared.b16 {%0,%1,%2,%3}, [%4];"
        : "=r"(r0), "=r"(r1), "=r"(r2), "=r"(r3) : "r"(a));
}
__device__ __forceinline__ void ldsm_x2(uint32_t& r0, uint32_t& r1, uint32_t a) {
    asm volatile("ldmatrix.sync.aligned.m8n8.x2.shared.b16 {%0,%1}, [%2];"
        : "=r"(r0), "=r"(r1) : "r"(a));
}
__device__ __forceinline__ void ldsm_x2t(uint32_t& r0, uint32_t& r1, uint32_t a) {
    asm volatile("ldmatrix.sync.aligned.m8n8.x2.trans.shared.b16 {%0,%1}, [%2];"
        : "=r"(r0), "=r"(r1) : "r"(a));
}
__device__ __forceinline__ void mma16(float c[4],
    uint32_t a0, uint32_t a1, uint32_t a2, uint32_t a3, uint32_t b0, uint32_t b1) {
    asm volatile("mma.sync.aligned.m16n8k16.row.col.f32.f16.f16.f32 "
        "{%0,%1,%2,%3}, {%4,%5,%6,%7}, {%8,%9}, {%0,%1,%2,%3};"
        : "+f"(c[0]), "+f"(c[1]), "+f"(c[2]), "+f"(c[3])
        : "r"(a0), "r"(a1), "r"(a2), "r"(a3), "r"(b0), "r"(b1));
}
// pack two fp32 into one fp16x2 register: lo = a, hi = b
__device__ __forceinline__ uint32_t packh2(float a, float b) {
    uint32_t u;
    asm("cvt.rn.f16x2.f32 %0, %1, %2;" : "=r"(u) : "f"(b), "f"(a));
    return u;
}

// ---------------- Kernel 0: pack intra weights into B-fragment layout ----------------
// grid = 32 x 256: idx over 4 mats x 2048 uint32
__global__ __launch_bounds__(256) void prep_w_kernel(
    const float* __restrict__ Wq, const float* __restrict__ Wk,
    const float* __restrict__ Wv, const float* __restrict__ Wo)
{
    const int idx = blockIdx.x * 256 + threadIdx.x;   // 0..8191
    const int mat = idx >> 11;
    const int t   = idx & 2047;
    const int lane2 = t & 63;        // 2*lane + j
    const int j = lane2 & 1, l = lane2 >> 1;
    const int tile = t >> 6;         // ntg*4 + kt
    const int kt = tile & 3, ntg = tile >> 2;
    const float* W = (mat == 0) ? Wq : (mat == 1) ? Wk : (mat == 2) ? Wv : Wo;
    const int row = 8 * ntg + (l >> 2);
    const int col = 16 * kt + 8 * j + 2 * (l & 3);
    g_wfrag[mat][t] = packh2(W[row * 64 + col], W[row * 64 + col + 1]);
}

// ---------------- Kernel 1: intra-group MHA (fp16 mma, global weight frags) ----------------
// grid = 4096 (b*256+g), 256 threads = 8 warps, dyn smem = 36864 B
__global__ __launch_bounds__(256, 3) void intra_kernel(
    const float* __restrict__ x, const int* __restrict__ part,
    const float* __restrict__ bq, const float* __restrict__ bk,
    const float* __restrict__ bv, const float* __restrict__ bo,
    float* __restrict__ out)
{
    extern __shared__ __half hsm[];
    float* stash = (float*)(hsm + QH_OFF);   // 64 x LDSF fp32 overlay (dead Q/K)

    const int tid = threadIdx.x;
    const int bb = blockIdx.x >> 8;
    const int g  = blockIdx.x & 255;
    const int* pg = part + (size_t)g * CC;
    const float* xb = x + (size_t)bb * NTOK * DD;

    const int lane = tid & 31, w = tid >> 5;
    const int mt = w & 3, nq = w >> 2;      // projection tiling: rows 16*mt, cols 32*nq
    const int r  = lane >> 2, cc = lane & 3;
    const int ln = lane & 7, sel = lane >> 3;
    // ldmatrix per-lane offsets (in halves)
    const int offA   = (ln + 8 * (sel & 1)) * PADH + 8 * (sel >> 1);  // A [m][k] x4
    const int offB2  = ln * PADH + 8 * (sel & 1);                     // B [n][k] x2
    const int offB2t = (lane & 15) * PADH;                            // B [k][n] x2.trans

    const uint32_t sbase = (uint32_t)__cvta_generic_to_shared(hsm);

    // ---- gather x (fp32 -> half) ----
#pragma unroll
    for (int k = 0; k < 4; ++k) {
        int f = tid + 256 * k;
        int row = f >> 4, c4 = f & 15;
        int tok = pg[row];
        float4 v = ((const float4*)(xb + (size_t)tok * DD))[c4];
        __half* d = hsm + XH_OFF + row * PADH + 4 * c4;
        *(half2*)(d)     = __floats2half2_rn(v.x, v.y);
        *(half2*)(d + 2) = __floats2half2_rn(v.z, v.w);
    }
    __syncthreads();

    // ---- A fragments of xs: shared by Q, K, V projections ----
    uint32_t xa[4][4];
#pragma unroll
    for (int kt = 0; kt < 4; ++kt)
        ldsm_x4(xa[kt][0], xa[kt][1], xa[kt][2], xa[kt][3],
                sbase + 2 * (XH_OFF + 16 * mt * PADH + 16 * kt + offA));

    const int row0 = 16 * mt + r;

    // ---- projection from global weight fragments ----
    auto projG = [&](int mat, const float* __restrict__ bias, int Doff, float scl) {
        const uint2* wf = (const uint2*)g_wfrag[mat];
        float acc[4][4] = {};
#pragma unroll
        for (int nt = 0; nt < 4; ++nt) {
            const int ntg = 4 * nq + nt;
#pragma unroll
            for (int kt = 0; kt < 4; ++kt) {
                uint2 f = wf[(ntg * 4 + kt) * 32 + lane];
                mma16(acc[nt], xa[kt][0], xa[kt][1], xa[kt][2], xa[kt][3], f.x, f.y);
            }
        }
#pragma unroll
        for (int nt = 0; nt < 4; ++nt) {
            const int n0 = 32 * nq + 8 * nt;
            float b0v = bias[n0 + 2 * cc], b1v = bias[n0 + 2 * cc + 1];
            *(half2*)(hsm + Doff + row0 * PADH + n0 + 2 * cc) =
                __floats2half2_rn((acc[nt][0] + b0v) * scl, (acc[nt][1] + b1v) * scl);
            *(half2*)(hsm + Doff + (row0 + 8) * PADH + n0 + 2 * cc) =
                __floats2half2_rn((acc[nt][2] + b0v) * scl, (acc[nt][3] + b1v) * scl);
        }
    };

    projG(0, bq, QH_OFF, 4.0f);
    projG(1, bk, KH_OFF, 1.0f);
    projG(2, bv, VH_OFF, 1.0f);
    __syncthreads();

    // ---- attention, fully register-resident; warp = (row-tile, head-pair lane) ----
    {
        const int hsel = w >> 2;
        const int arow = 16 * mt;
#pragma unroll
        for (int hp = 0; hp < 2; ++hp) {
            const int h = 2 * hp + hsel;
            const int hq = 16 * h;
            // scores: S = Qh @ Kh^T (Q pre-scaled by 4)
            uint32_t a0, a1, a2, a3;
            ldsm_x4(a0, a1, a2, a3, sbase + 2 * (QH_OFF + arow * PADH + hq + offA));
            float s[8][4];
#pragma unroll
            for (int nt = 0; nt < 8; ++nt) {
                uint32_t b0, b1;
                ldsm_x2(b0, b1, sbase + 2 * (KH_OFF + 8 * nt * PADH + hq + offB2));
                s[nt][0] = s[nt][1] = s[nt][2] = s[nt][3] = 0.f;
                mma16(s[nt], a0, a1, a2, a3, b0, b1);
            }
            // softmax: row r ([0],[1]) and row r+8 ([2],[3]); quad shuffles
            float mx0 = -1e30f, mx1 = -1e30f;
#pragma unroll
            for (int nt = 0; nt < 8; ++nt) {
                mx0 = fmaxf(mx0, fmaxf(s[nt][0], s[nt][1]));
                mx1 = fmaxf(mx1, fmaxf(s[nt][2], s[nt][3]));
            }
            mx0 = fmaxf(mx0, __shfl_xor_sync(0xffffffffu, mx0, 1));
            mx0 = fmaxf(mx0, __shfl_xor_sync(0xffffffffu, mx0, 2));
            mx1 = fmaxf(mx1, __shfl_xor_sync(0xffffffffu, mx1, 1));
            mx1 = fmaxf(mx1, __shfl_xor_sync(0xffffffffu, mx1, 2));
            float sum0 = 0.f, sum1 = 0.f;
#pragma unroll
            for (int nt = 0; nt < 8; ++nt) {
                s[nt][0] = __expf(s[nt][0] - mx0); sum0 += s[nt][0];
                s[nt][1] = __expf(s[nt][1] - mx0); sum0 += s[nt][1];
                s[nt][2] = __expf(s[nt][2] - mx1); sum1 += s[nt][2];
                s[nt][3] = __expf(s[nt][3] - mx1); sum1 += s[nt][3];
            }
            sum0 += __shfl_xor_sync(0xffffffffu, sum0, 1);
            sum0 += __shfl_xor_sync(0xffffffffu, sum0, 2);
            sum1 += __shfl_xor_sync(0xffffffffu, sum1, 1);
            sum1 += __shfl_xor_sync(0xffffffffu, sum1, 2);
            const float inv0 = 1.f / sum0, inv1 = 1.f / sum1;
            // AV: P fragments packed directly from score accumulators
            float o[2][4] = {};
#pragma unroll
            for (int kc = 0; kc < 4; ++kc) {
                uint32_t pa0 = packh2(s[2*kc][0] * inv0, s[2*kc][1] * inv0);
                uint32_t pa1 = packh2(s[2*kc][2] * inv1, s[2*kc][3] * inv1);
                uint32_t pa2 = packh2(s[2*kc+1][0] * inv0, s[2*kc+1][1] * inv0);
                uint32_t pa3 = packh2(s[2*kc+1][2] * inv1, s[2*kc+1][3] * inv1);
#pragma unroll
                for (int nt2 = 0; nt2 < 2; ++nt2) {
                    uint32_t b0, b1;
                    ldsm_x2t(b0, b1, sbase + 2 * (VH_OFF + 16 * kc * PADH + hq + 8 * nt2 + offB2t));
                    mma16(o[nt2], pa0, pa1, pa2, pa3, b0, b1);
                }
            }
#pragma unroll
            for (int nt2 = 0; nt2 < 2; ++nt2) {
                const int n0 = hq + 8 * nt2 + 2 * cc;
                *(half2*)(hsm + XH_OFF + (arow + r) * PADH + n0) =
                    __floats2half2_rn(o[nt2][0], o[nt2][1]);
                *(half2*)(hsm + XH_OFF + (arow + r + 8) * PADH + n0) =
                    __floats2half2_rn(o[nt2][2], o[nt2][3]);
            }
        }
    }
    __syncthreads();

    // ---- O projection (+bias) -> gmem scatter + fp32 stash -> pooled max ----
    {
#pragma unroll
        for (int kt = 0; kt < 4; ++kt)
            ldsm_x4(xa[kt][0], xa[kt][1], xa[kt][2], xa[kt][3],
                    sbase + 2 * (XH_OFF + 16 * mt * PADH + 16 * kt + offA));
        const uint2* wf = (const uint2*)g_wfrag[3];
        float acc[4][4] = {};
#pragma unroll
        for (int nt = 0; nt < 4; ++nt) {
            const int ntg = 4 * nq + nt;
#pragma unroll
            for (int kt = 0; kt < 4; ++kt) {
                uint2 f = wf[(ntg * 4 + kt) * 32 + lane];
                mma16(acc[nt], xa[kt][0], xa[kt][1], xa[kt][2], xa[kt][3], f.x, f.y);
            }
        }
        const int tokA = pg[row0], tokB = pg[row0 + 8];
        float* oA = out + ((size_t)bb * NTOK + tokA) * DD;
        float* oB = out + ((size_t)bb * NTOK + tokB) * DD;
#pragma unroll
        for (int nt = 0; nt < 4; ++nt) {
            const int n0 = 32 * nq + 8 * nt;
            float b0v = bo[n0 + 2 * cc], b1v = bo[n0 + 2 * cc + 1];
            float v0 = acc[nt][0] + b0v, v1 = acc[nt][1] + b1v;
            float v2 = acc[nt][2] + b0v, v3 = acc[nt][3] + b1v;
            *(float2*)(oA + n0 + 2 * cc) = make_float2(v0, v1);
            *(float2*)(oB + n0 + 2 * cc) = make_float2(v2, v3);
            *(float2*)&stash[row0 * LDSF + n0 + 2 * cc]       = make_float2(v0, v1);
            *(float2*)&stash[(row0 + 8) * LDSF + n0 + 2 * cc] = make_float2(v2, v3);
        }
    }
    __syncthreads();
    if (tid < 64) {
        float m = stash[tid];
#pragma unroll 8
        for (int n = 1; n < 64; ++n) m = fmaxf(m, stash[n * LDSF + tid]);
        g_pooled[((size_t)bb * GG + g) * DD + tid] = m;
    }
}

// ---------------- helpers for fp32 inter path ----------------
__device__ __forceinline__ void fma16f(float acc[4][4], const float4 a[4], const float4 w[4]) {
#pragma unroll
    for (int i = 0; i < 4; ++i)
#pragma unroll
        for (int j = 0; j < 4; ++j) {
            acc[i][j] = fmaf(a[i].x, w[j].x, acc[i][j]);
            acc[i][j] = fmaf(a[i].y, w[j].y, acc[i][j]);
            acc[i][j] = fmaf(a[i].z, w[j].z, acc[i][j]);
            acc[i][j] = fmaf(a[i].w, w[j].w, acc[i][j]);
        }
}

// ---------------- Kernel 2: inter QKV projections ----------------
__global__ __launch_bounds__(256) void inter_qkv_kernel(
    const float* __restrict__ Wq, const float* __restrict__ bq,
    const float* __restrict__ Wk, const float* __restrict__ bk,
    const float* __restrict__ Wv, const float* __restrict__ bv)
{
    __shared__ float As[64 * LDSF];
    __shared__ float ws[64 * LDSF];
    const int tid = threadIdx.x;
    const int blk = blockIdx.x;
    const int wsel = blk >> 6;
    const int b = (blk >> 2) & 15;
    const int quarter = blk & 3;
    const float* W = (wsel == 0) ? Wq : ((wsel == 1) ? Wk : Wv);
    const float* bias = (wsel == 0) ? bq : ((wsel == 1) ? bk : bv);
    const float* A = g_pooled + ((size_t)b * GG + quarter * 64) * DD;
    float* dst = g_qkv + ((size_t)(wsel * BB + b) * GG + quarter * 64) * DD;

#pragma unroll
    for (int k = 0; k < 4; ++k) {
        int f = tid + 256 * k;
        int r = f >> 4, c4 = f & 15;
        *(float4*)&As[r * LDSF + 4 * c4] = ((const float4*)(A + r * 64))[c4];
        *(float4*)&ws[r * LDSF + 4 * c4] = ((const float4*)(W + r * 64))[c4];
    }
    __syncthreads();

    const int tn = tid >> 4, to = tid & 15;
    float acc[4][4] = {};
#pragma unroll 4
    for (int d4 = 0; d4 < 64; d4 += 4) {
        float4 a[4], w[4];
#pragma unroll
        for (int i = 0; i < 4; ++i) a[i] = *(const float4*)&As[(4 * tn + i) * LDSF + d4];
#pragma unroll
        for (int j = 0; j < 4; ++j) w[j] = *(const float4*)&ws[(4 * to + j) * LDSF + d4];
        fma16f(acc, a, w);
    }
    float bj[4];
#pragma unroll
    for (int j = 0; j < 4; ++j) bj[j] = bias[4 * to + j];
#pragma unroll
    for (int i = 0; i < 4; ++i) {
        float4 v;
        v.x = acc[i][0] + bj[0];
        v.y = acc[i][1] + bj[1];
        v.z = acc[i][2] + bj[2];
        v.w = acc[i][3] + bj[3];
        *(float4*)&dst[(4 * tn + i) * 64 + 4 * to] = v;
    }
}

// ---------------- Kernel 3: inter attention (+ O proj) ----------------
__global__ __launch_bounds__(128) void inter_attn_kernel(
    const float* __restrict__ Wo, const float* __restrict__ bo)
{
    extern __shared__ float sm2[];
    float* ksm = sm2;
    float* vsm = sm2 + 256 * LDSF;
    float* ss  = sm2 + 2 * 256 * LDSF;  // 4 * 264
    float* sq  = ss + 4 * 264;          // 64
    float* so  = sq + 64;               // 64

    const int tid = threadIdx.x;
    const int b = blockIdx.x >> 4;
    const int chunk = blockIdx.x & 15;

    const float* qb = g_qkv + (size_t)(0 * BB + b) * GG * DD;
    const float* kb = g_qkv + (size_t)(1 * BB + b) * GG * DD;
    const float* vb = g_qkv + (size_t)(2 * BB + b) * GG * DD;

#pragma unroll
    for (int k = 0; k < 32; ++k) {
        int f = tid + 128 * k;
        int row = f >> 4, c4 = f & 15;
        *(float4*)&ksm[row * LDSF + 4 * c4] = ((const float4*)(kb + row * 64))[c4];
        *(float4*)&vsm[row * LDSF + 4 * c4] = ((const float4*)(vb + row * 64))[c4];
    }
    __syncthreads();

    const int warp = tid >> 5, lane = tid & 31;

    for (int t0 = 0; t0 < 16; ++t0) {
        const int n = chunk * 16 + t0;
        if (tid < 64) sq[tid] = qb[n * 64 + tid];
        __syncthreads();

        const int hq = warp * 16;
        float4 q0 = *(const float4*)&sq[hq];
        float4 q1 = *(const float4*)&sq[hq + 4];
        float4 q2 = *(const float4*)&sq[hq + 8];
        float4 q3 = *(const float4*)&sq[hq + 12];
        float vals[8];
#pragma unroll
        for (int k = 0; k < 8; ++k) {
            int m = lane + 32 * k;
            const float* kr = ksm + m * LDSF + hq;
            float4 k0 = *(const float4*)kr;
            float4 k1 = *(const float4*)(kr + 4);
            float4 k2 = *(const float4*)(kr + 8);
            float4 k3 = *(const float4*)(kr + 12);
            float s = q0.x * k0.x + q0.y * k0.y + q0.z * k0.z + q0.w * k0.w
                    + q1.x * k1.x + q1.y * k1.y + q1.z * k1.z + q1.w * k1.w
                    + q2.x * k2.x + q2.y * k2.y + q2.z * k2.z + q2.w * k2.w
                    + q3.x * k3.x + q3.y * k3.y + q3.z * k3.z + q3.w * k3.w;
            vals[k] = 4.0f * s;
        }
        float mx = vals[0];
#pragma unroll
        for (int k = 1; k < 8; ++k) mx = fmaxf(mx, vals[k]);
#pragma unroll
        for (int off = 16; off; off >>= 1) mx = fmaxf(mx, __shfl_xor_sync(0xffffffffu, mx, off));
        float sum = 0.f;
#pragma unroll
        for (int k = 0; k < 8; ++k) { vals[k] = __expf(vals[k] - mx); sum += vals[k]; }
#pragma unroll
        for (int off = 16; off; off >>= 1) sum += __shfl_xor_sync(0xffffffffu, sum, off);
        float inv = 1.f / sum;
#pragma unroll
        for (int k = 0; k < 8; ++k) ss[warp * 264 + lane + 32 * k] = vals[k] * inv;
        __syncthreads();

        if (tid < 64) {
            const int h = tid >> 4, dd = tid & 15;
            const float* pr = ss + h * 264;
            const float* vr = vsm + h * 16 + dd;
            float acc = 0.f;
#pragma unroll 8
            for (int m = 0; m < 256; ++m) acc = fmaf(pr[m], vr[m * LDSF], acc);
            so[tid] = acc;
        }
        __syncthreads();

        if (tid < 64) {
            const float* wr = Wo + tid * 64;
            float acc = bo[tid];
#pragma unroll 8
            for (int d = 0; d < 64; ++d) acc = fmaf(so[d], wr[d], acc);
            g_inter[((size_t)b * GG + n) * DD + tid] = acc;
        }
        __syncthreads();
    }
}

// ---------------- Kernel 4: broadcast-add inter, scattered ----------------
__global__ __launch_bounds__(256) void add_scatter_kernel(
    const int* __restrict__ part, float* __restrict__ out)
{
    __shared__ __align__(16) float iv[64];
    __shared__ int toks[64];
    const int tid = threadIdx.x;
    const int b = blockIdx.x >> 8;
    const int g = blockIdx.x & 255;
    if (tid < 64) iv[tid] = g_inter[((size_t)b * GG + g) * DD + tid];
    else if (tid < 128) toks[tid - 64] = part[(size_t)g * CC + (tid - 64)];
    __syncthreads();
#pragma unroll
    for (int k = 0; k < 4; ++k) {
        int f = tid + 256 * k;
        int row = f >> 4, c4 = f & 15;
        float* p = out + ((size_t)b * NTOK + toks[row]) * DD + 4 * c4;
        float4 v = *(float4*)p;
        float4 a = *(const float4*)&iv[4 * c4];
        v.x += a.x; v.y += a.y; v.z += a.z; v.w += a.w;
        *(float4*)p = v;
    }
}

// ---------------- launch ----------------
extern "C" void kernel_launch(void* const* d_in, const int* in_sizes, int n_in,
                              void* d_out, int out_size)
{
    (void)in_sizes; (void)n_in; (void)out_size;
    const float* x    = (const float*)d_in[0];
    const int*   part = (const int*)d_in[1];   // int32 on device (JAX x64 disabled)
    const float* Wq_a = (const float*)d_in[2];
    const float* bq_a = (const float*)d_in[3];
    const float* Wk_a = (const float*)d_in[4];
    const float* bk_a = (const float*)d_in[5];
    const float* Wv_a = (const float*)d_in[6];
    const float* bv_a = (const float*)d_in[7];
    const float* Wo_a = (const float*)d_in[8];
    const float* bo_a = (const float*)d_in[9];
    const float* Wq_i = (const float*)d_in[10];
    const float* bq_i = (const float*)d_in[11];
    const float* Wk_i = (const float*)d_in[12];
    const float* bk_i = (const float*)d_in[13];
    const float* Wv_i = (const float*)d_in[14];
    const float* bv_i = (const float*)d_in[15];
    const float* Wo_i = (const float*)d_in[16];
    const float* bo_i = (const float*)d_in[17];
    float* out = (float*)d_out;

    const int smem_intra = SMEM_INTRA_BYTES;                                      // 36864 B
    const int smem_iatt  = (2 * 256 * LDSF + 4 * 264 + 128) * (int)sizeof(float); // 144000 B
    cudaFuncSetAttribute(intra_kernel, cudaFuncAttributeMaxDynamicSharedMemorySize, smem_intra);
    cudaFuncSetAttribute(inter_attn_kernel, cudaFuncAttributeMaxDynamicSharedMemorySize, smem_iatt);

    prep_w_kernel<<<32, 256>>>(Wq_a, Wk_a, Wv_a, Wo_a);
    intra_kernel<<<BB * GG, 256, smem_intra>>>(x, part,
        bq_a, bk_a, bv_a, bo_a, out);
    inter_qkv_kernel<<<192, 256>>>(Wq_i, bq_i, Wk_i, bk_i, Wv_i, bv_i);
    inter_attn_kernel<<<256, 128, smem_iatt>>>(Wo_i, bo_i);
    add_scatter_kernel<<<BB * GG, 256>>>(part, out);
}

// round 11
// speedup vs baseline: 4.1445x; 2.2946x over previous
#include <cuda_runtime.h>
#include <cuda_fp16.h>
#include <cstdint>

// Problem constants (fixed by the dataset)
constexpr int BB   = 16;     // batch
constexpr int NTOK = 16384;  // tokens
constexpr int DD   = 64;     // model dim (= dhf)
constexpr int GG   = 256;    // groups
constexpr int CC   = 64;     // tokens per group
constexpr int NH   = 4;      // heads
// SCALE = 4.0 multiplies scores; folded into Q at fp16 staging (exact: power of two)

#define PADH 72   // half-precision smem row stride (144 B, ldmatrix conflict-free)
#define LDSF 68   // fp32 smem row stride (pooled-max stash, inter_qkv)

// intra smem layout (half indices)
#define XH_OFF 0
#define QH_OFF 4608
#define KH_OFF 9216
#define VH_OFF 13824
#define SMEM_INTRA_BYTES (4 * 4608 * 2)   // 36864 B

// inter-attn smem layout (half indices)
#define QI_OFF 0
#define KI_OFF 4608
#define VI_OFF 23040
#define SMEM_IATT_BYTES ((23040 + 18432) * 2)   // 82944 B

// ---------------- scratch (no allocations allowed) ----------------
__device__ float g_pooled[BB * GG * DD];      // 1 MiB
__device__ float g_qkv[3 * BB * GG * DD];     // 3 MiB  [q/k/v][b][n][d]
__device__ float g_inter[BB * GG * DD];       // 1 MiB
// pre-packed fp16 weight fragments: [mat][(ntg*4+kt)*64 + 2*lane + j]
// mats: 0=Wq_a 1=Wk_a 2=Wv_a 3=Wo_a 4=Wo_i
__device__ uint32_t g_wfrag[5][2048];         // 40 KiB

// ---------------- mma / ldmatrix helpers ----------------
__device__ __forceinline__ void ldsm_x4(uint32_t& r0, uint32_t& r1, uint32_t& r2, uint32_t& r3, uint32_t a) {
    asm volatile("ldmatrix.sync.aligned.m8n8.x4.shared.b16 {%0,%1,%2,%3}, [%4];"
        : "=r"(r0), "=r"(r1), "=r"(r2), "=r"(r3) : "r"(a));
}
__device__ __forceinline__ void ldsm_x2(uint32_t& r0, uint32_t& r1, uint32_t a) {
    asm volatile("ldmatrix.sync.aligned.m8n8.x2.shared.b16 {%0,%1}, [%2];"
        : "=r"(r0), "=r"(r1) : "r"(a));
}
__device__ __forceinline__ void ldsm_x2t(uint32_t& r0, uint32_t& r1, uint32_t a) {
    asm volatile("ldmatrix.sync.aligned.m8n8.x2.trans.shared.b16 {%0,%1}, [%2];"
        : "=r"(r0), "=r"(r1) : "r"(a));
}
__device__ __forceinline__ void mma16(float c[4],
    uint32_t a0, uint32_t a1, uint32_t a2, uint32_t a3, uint32_t b0, uint32_t b1) {
    asm volatile("mma.sync.aligned.m16n8k16.row.col.f32.f16.f16.f32 "
        "{%0,%1,%2,%3}, {%4,%5,%6,%7}, {%8,%9}, {%0,%1,%2,%3};"
        : "+f"(c[0]), "+f"(c[1]), "+f"(c[2]), "+f"(c[3])
        : "r"(a0), "r"(a1), "r"(a2), "r"(a3), "r"(b0), "r"(b1));
}
// pack two fp32 into one fp16x2 register: lo = a, hi = b
__device__ __forceinline__ uint32_t packh2(float a, float b) {
    uint32_t u;
    asm("cvt.rn.f16x2.f32 %0, %1, %2;" : "=r"(u) : "f"(b), "f"(a));
    return u;
}

// ---------------- Kernel 0: pack weights into B-fragment layout ----------------
// grid = 40 x 256: idx over 5 mats x 2048 uint32
__global__ __launch_bounds__(256) void prep_w_kernel(
    const float* __restrict__ Wq, const float* __restrict__ Wk,
    const float* __restrict__ Wv, const float* __restrict__ Wo,
    const float* __restrict__ Woi)
{
    const int idx = blockIdx.x * 256 + threadIdx.x;   // 0..10239
    const int mat = idx >> 11;
    const int t   = idx & 2047;
    const int lane2 = t & 63;        // 2*lane + j
    const int j = lane2 & 1, l = lane2 >> 1;
    const int tile = t >> 6;         // ntg*4 + kt
    const int kt = tile & 3, ntg = tile >> 2;
    const float* W = (mat == 0) ? Wq : (mat == 1) ? Wk : (mat == 2) ? Wv : (mat == 3) ? Wo : Woi;
    const int row = 8 * ntg + (l >> 2);
    const int col = 16 * kt + 8 * j + 2 * (l & 3);
    g_wfrag[mat][t] = packh2(W[row * 64 + col], W[row * 64 + col + 1]);
}

// ---------------- Kernel 1: intra-group MHA (fp16 mma, global weight frags) ----------------
// grid = 4096 (b*256+g), 256 threads = 8 warps, dyn smem = 36864 B
__global__ __launch_bounds__(256, 3) void intra_kernel(
    const float* __restrict__ x, const int* __restrict__ part,
    const float* __restrict__ bq, const float* __restrict__ bk,
    const float* __restrict__ bv, const float* __restrict__ bo,
    float* __restrict__ out)
{
    extern __shared__ __half hsm[];
    float* stash = (float*)(hsm + QH_OFF);   // 64 x LDSF fp32 overlay (dead Q/K)

    const int tid = threadIdx.x;
    const int bb = blockIdx.x >> 8;
    const int g  = blockIdx.x & 255;
    const int* pg = part + (size_t)g * CC;
    const float* xb = x + (size_t)bb * NTOK * DD;

    const int lane = tid & 31, w = tid >> 5;
    const int mt = w & 3, nq = w >> 2;
    const int r  = lane >> 2, cc = lane & 3;
    const int ln = lane & 7, sel = lane >> 3;
    const int offA   = (ln + 8 * (sel & 1)) * PADH + 8 * (sel >> 1);
    const int offB2  = ln * PADH + 8 * (sel & 1);
    const int offB2t = (lane & 15) * PADH;

    const uint32_t sbase = (uint32_t)__cvta_generic_to_shared(hsm);

    // ---- gather x (fp32 -> half) ----
#pragma unroll
    for (int k = 0; k < 4; ++k) {
        int f = tid + 256 * k;
        int row = f >> 4, c4 = f & 15;
        int tok = pg[row];
        float4 v = ((const float4*)(xb + (size_t)tok * DD))[c4];
        __half* d = hsm + XH_OFF + row * PADH + 4 * c4;
        *(half2*)(d)     = __floats2half2_rn(v.x, v.y);
        *(half2*)(d + 2) = __floats2half2_rn(v.z, v.w);
    }
    __syncthreads();

    // ---- A fragments of xs: shared by Q, K, V projections ----
    uint32_t xa[4][4];
#pragma unroll
    for (int kt = 0; kt < 4; ++kt)
        ldsm_x4(xa[kt][0], xa[kt][1], xa[kt][2], xa[kt][3],
                sbase + 2 * (XH_OFF + 16 * mt * PADH + 16 * kt + offA));

    const int row0 = 16 * mt + r;

    auto projG = [&](int mat, const float* __restrict__ bias, int Doff, float scl) {
        const uint2* wf = (const uint2*)g_wfrag[mat];
        float acc[4][4] = {};
#pragma unroll
        for (int nt = 0; nt < 4; ++nt) {
            const int ntg = 4 * nq + nt;
#pragma unroll
            for (int kt = 0; kt < 4; ++kt) {
                uint2 f = wf[(ntg * 4 + kt) * 32 + lane];
                mma16(acc[nt], xa[kt][0], xa[kt][1], xa[kt][2], xa[kt][3], f.x, f.y);
            }
        }
#pragma unroll
        for (int nt = 0; nt < 4; ++nt) {
            const int n0 = 32 * nq + 8 * nt;
            float b0v = bias[n0 + 2 * cc], b1v = bias[n0 + 2 * cc + 1];
            *(half2*)(hsm + Doff + row0 * PADH + n0 + 2 * cc) =
                __floats2half2_rn((acc[nt][0] + b0v) * scl, (acc[nt][1] + b1v) * scl);
            *(half2*)(hsm + Doff + (row0 + 8) * PADH + n0 + 2 * cc) =
                __floats2half2_rn((acc[nt][2] + b0v) * scl, (acc[nt][3] + b1v) * scl);
        }
    };

    projG(0, bq, QH_OFF, 4.0f);
    projG(1, bk, KH_OFF, 1.0f);
    projG(2, bv, VH_OFF, 1.0f);
    __syncthreads();

    // ---- attention, register-resident ----
    {
        const int hsel = w >> 2;
        const int arow = 16 * mt;
#pragma unroll
        for (int hp = 0; hp < 2; ++hp) {
            const int h = 2 * hp + hsel;
            const int hq = 16 * h;
            uint32_t a0, a1, a2, a3;
            ldsm_x4(a0, a1, a2, a3, sbase + 2 * (QH_OFF + arow * PADH + hq + offA));
            float s[8][4];
#pragma unroll
            for (int nt = 0; nt < 8; ++nt) {
                uint32_t b0, b1;
                ldsm_x2(b0, b1, sbase + 2 * (KH_OFF + 8 * nt * PADH + hq + offB2));
                s[nt][0] = s[nt][1] = s[nt][2] = s[nt][3] = 0.f;
                mma16(s[nt], a0, a1, a2, a3, b0, b1);
            }
            float mx0 = -1e30f, mx1 = -1e30f;
#pragma unroll
            for (int nt = 0; nt < 8; ++nt) {
                mx0 = fmaxf(mx0, fmaxf(s[nt][0], s[nt][1]));
                mx1 = fmaxf(mx1, fmaxf(s[nt][2], s[nt][3]));
            }
            mx0 = fmaxf(mx0, __shfl_xor_sync(0xffffffffu, mx0, 1));
            mx0 = fmaxf(mx0, __shfl_xor_sync(0xffffffffu, mx0, 2));
            mx1 = fmaxf(mx1, __shfl_xor_sync(0xffffffffu, mx1, 1));
            mx1 = fmaxf(mx1, __shfl_xor_sync(0xffffffffu, mx1, 2));
            float sum0 = 0.f, sum1 = 0.f;
#pragma unroll
            for (int nt = 0; nt < 8; ++nt) {
                s[nt][0] = __expf(s[nt][0] - mx0); sum0 += s[nt][0];
                s[nt][1] = __expf(s[nt][1] - mx0); sum0 += s[nt][1];
                s[nt][2] = __expf(s[nt][2] - mx1); sum1 += s[nt][2];
                s[nt][3] = __expf(s[nt][3] - mx1); sum1 += s[nt][3];
            }
            sum0 += __shfl_xor_sync(0xffffffffu, sum0, 1);
            sum0 += __shfl_xor_sync(0xffffffffu, sum0, 2);
            sum1 += __shfl_xor_sync(0xffffffffu, sum1, 1);
            sum1 += __shfl_xor_sync(0xffffffffu, sum1, 2);
            const float inv0 = 1.f / sum0, inv1 = 1.f / sum1;
            float o[2][4] = {};
#pragma unroll
            for (int kc = 0; kc < 4; ++kc) {
                uint32_t pa0 = packh2(s[2*kc][0] * inv0, s[2*kc][1] * inv0);
                uint32_t pa1 = packh2(s[2*kc][2] * inv1, s[2*kc][3] * inv1);
                uint32_t pa2 = packh2(s[2*kc+1][0] * inv0, s[2*kc+1][1] * inv0);
                uint32_t pa3 = packh2(s[2*kc+1][2] * inv1, s[2*kc+1][3] * inv1);
#pragma unroll
                for (int nt2 = 0; nt2 < 2; ++nt2) {
                    uint32_t b0, b1;
                    ldsm_x2t(b0, b1, sbase + 2 * (VH_OFF + 16 * kc * PADH + hq + 8 * nt2 + offB2t));
                    mma16(o[nt2], pa0, pa1, pa2, pa3, b0, b1);
                }
            }
#pragma unroll
            for (int nt2 = 0; nt2 < 2; ++nt2) {
                const int n0 = hq + 8 * nt2 + 2 * cc;
                *(half2*)(hsm + XH_OFF + (arow + r) * PADH + n0) =
                    __floats2half2_rn(o[nt2][0], o[nt2][1]);
                *(half2*)(hsm + XH_OFF + (arow + r + 8) * PADH + n0) =
                    __floats2half2_rn(o[nt2][2], o[nt2][3]);
            }
        }
    }
    __syncthreads();

    // ---- O projection (+bias) -> gmem scatter + fp32 stash -> pooled max ----
    {
#pragma unroll
        for (int kt = 0; kt < 4; ++kt)
            ldsm_x4(xa[kt][0], xa[kt][1], xa[kt][2], xa[kt][3],
                    sbase + 2 * (XH_OFF + 16 * mt * PADH + 16 * kt + offA));
        const uint2* wf = (const uint2*)g_wfrag[3];
        float acc[4][4] = {};
#pragma unroll
        for (int nt = 0; nt < 4; ++nt) {
            const int ntg = 4 * nq + nt;
#pragma unroll
            for (int kt = 0; kt < 4; ++kt) {
                uint2 f = wf[(ntg * 4 + kt) * 32 + lane];
                mma16(acc[nt], xa[kt][0], xa[kt][1], xa[kt][2], xa[kt][3], f.x, f.y);
            }
        }
        const int tokA = pg[row0], tokB = pg[row0 + 8];
        float* oA = out + ((size_t)bb * NTOK + tokA) * DD;
        float* oB = out + ((size_t)bb * NTOK + tokB) * DD;
#pragma unroll
        for (int nt = 0; nt < 4; ++nt) {
            const int n0 = 32 * nq + 8 * nt;
            float b0v = bo[n0 + 2 * cc], b1v = bo[n0 + 2 * cc + 1];
            float v0 = acc[nt][0] + b0v, v1 = acc[nt][1] + b1v;
            float v2 = acc[nt][2] + b0v, v3 = acc[nt][3] + b1v;
            *(float2*)(oA + n0 + 2 * cc) = make_float2(v0, v1);
            *(float2*)(oB + n0 + 2 * cc) = make_float2(v2, v3);
            *(float2*)&stash[row0 * LDSF + n0 + 2 * cc]       = make_float2(v0, v1);
            *(float2*)&stash[(row0 + 8) * LDSF + n0 + 2 * cc] = make_float2(v2, v3);
        }
    }
    __syncthreads();
    if (tid < 64) {
        float m = stash[tid];
#pragma unroll 8
        for (int n = 1; n < 64; ++n) m = fmaxf(m, stash[n * LDSF + tid]);
        g_pooled[((size_t)bb * GG + g) * DD + tid] = m;
    }
}

// ---------------- helpers for fp32 inter path ----------------
__device__ __forceinline__ void fma16f(float acc[4][4], const float4 a[4], const float4 w[4]) {
#pragma unroll
    for (int i = 0; i < 4; ++i)
#pragma unroll
        for (int j = 0; j < 4; ++j) {
            acc[i][j] = fmaf(a[i].x, w[j].x, acc[i][j]);
            acc[i][j] = fmaf(a[i].y, w[j].y, acc[i][j]);
            acc[i][j] = fmaf(a[i].z, w[j].z, acc[i][j]);
            acc[i][j] = fmaf(a[i].w, w[j].w, acc[i][j]);
        }
}

// ---------------- Kernel 2: inter QKV projections (fp32) ----------------
__global__ __launch_bounds__(256) void inter_qkv_kernel(
    const float* __restrict__ Wq, const float* __restrict__ bq,
    const float* __restrict__ Wk, const float* __restrict__ bk,
    const float* __restrict__ Wv, const float* __restrict__ bv)
{
    __shared__ float As[64 * LDSF];
    __shared__ float ws[64 * LDSF];
    const int tid = threadIdx.x;
    const int blk = blockIdx.x;
    const int wsel = blk >> 6;
    const int b = (blk >> 2) & 15;
    const int quarter = blk & 3;
    const float* W = (wsel == 0) ? Wq : ((wsel == 1) ? Wk : Wv);
    const float* bias = (wsel == 0) ? bq : ((wsel == 1) ? bk : bv);
    const float* A = g_pooled + ((size_t)b * GG + quarter * 64) * DD;
    float* dst = g_qkv + ((size_t)(wsel * BB + b) * GG + quarter * 64) * DD;

#pragma unroll
    for (int k = 0; k < 4; ++k) {
        int f = tid + 256 * k;
        int r = f >> 4, c4 = f & 15;
        *(float4*)&As[r * LDSF + 4 * c4] = ((const float4*)(A + r * 64))[c4];
        *(float4*)&ws[r * LDSF + 4 * c4] = ((const float4*)(W + r * 64))[c4];
    }
    __syncthreads();

    const int tn = tid >> 4, to = tid & 15;
    float acc[4][4] = {};
#pragma unroll 4
    for (int d4 = 0; d4 < 64; d4 += 4) {
        float4 a[4], w[4];
#pragma unroll
        for (int i = 0; i < 4; ++i) a[i] = *(const float4*)&As[(4 * tn + i) * LDSF + d4];
#pragma unroll
        for (int j = 0; j < 4; ++j) w[j] = *(const float4*)&ws[(4 * to + j) * LDSF + d4];
        fma16f(acc, a, w);
    }
    float bj[4];
#pragma unroll
    for (int j = 0; j < 4; ++j) bj[j] = bias[4 * to + j];
#pragma unroll
    for (int i = 0; i < 4; ++i) {
        float4 v;
        v.x = acc[i][0] + bj[0];
        v.y = acc[i][1] + bj[1];
        v.z = acc[i][2] + bj[2];
        v.w = acc[i][3] + bj[3];
        *(float4*)&dst[(4 * tn + i) * 64 + 4 * to] = v;
    }
}

// ---------------- Kernel 3: inter attention (fp16 mma, flash over 2 key chunks) ----------------
// grid = 64 (b = blk>>2, qchunk = blk&3), 256 threads = 8 warps, dyn smem = 82944 B
__global__ __launch_bounds__(256) void inter_attn_mma(
    const float* __restrict__ bo)
{
    extern __shared__ __half hsm[];
    const int tid = threadIdx.x;
    const int b  = blockIdx.x >> 2;
    const int qc = blockIdx.x & 3;

    const int lane = tid & 31, w = tid >> 5;
    const int mt = w & 3, nq = w >> 2;
    const int r  = lane >> 2, cc = lane & 3;
    const int ln = lane & 7, sel = lane >> 3;
    const int offA   = (ln + 8 * (sel & 1)) * PADH + 8 * (sel >> 1);
    const int offB2  = ln * PADH + 8 * (sel & 1);
    const int offB2t = (lane & 15) * PADH;
    const uint32_t sbase = (uint32_t)__cvta_generic_to_shared(hsm);

    const float* qb = g_qkv + (size_t)(0 * BB + b) * GG * DD + (size_t)qc * 64 * DD;
    const float* kb = g_qkv + (size_t)(1 * BB + b) * GG * DD;
    const float* vb = g_qkv + (size_t)(2 * BB + b) * GG * DD;

    // ---- stage Q (x4 scale folded), K, V as fp16 ----
#pragma unroll
    for (int k = 0; k < 4; ++k) {
        int f = tid + 256 * k;
        int row = f >> 4, c4 = f & 15;
        float4 v = ((const float4*)(qb + row * 64))[c4];
        __half* d = hsm + QI_OFF + row * PADH + 4 * c4;
        *(half2*)(d)     = __floats2half2_rn(4.f * v.x, 4.f * v.y);
        *(half2*)(d + 2) = __floats2half2_rn(4.f * v.z, 4.f * v.w);
    }
#pragma unroll
    for (int k = 0; k < 16; ++k) {
        int f = tid + 256 * k;
        int row = f >> 4, c4 = f & 15;
        float4 v = ((const float4*)(kb + row * 64))[c4];
        __half* d = hsm + KI_OFF + row * PADH + 4 * c4;
        *(half2*)(d)     = __floats2half2_rn(v.x, v.y);
        *(half2*)(d + 2) = __floats2half2_rn(v.z, v.w);
        float4 u = ((const float4*)(vb + row * 64))[c4];
        __half* e = hsm + VI_OFF + row * PADH + 4 * c4;
        *(half2*)(e)     = __floats2half2_rn(u.x, u.y);
        *(half2*)(e + 2) = __floats2half2_rn(u.z, u.w);
    }
    __syncthreads();

    // ---- flash attention: warp = (mt rows, hsel head-pair), 256 keys in 2 chunks ----
    {
        const int hsel = w >> 2;
        const int arow = 16 * mt;
#pragma unroll 1
        for (int hp = 0; hp < 2; ++hp) {
            const int h = 2 * hp + hsel;
            const int hq = 16 * h;
            uint32_t a0, a1, a2, a3;
            ldsm_x4(a0, a1, a2, a3, sbase + 2 * (QI_OFF + arow * PADH + hq + offA));
            float o[2][4] = {};
            float m0 = -1e30f, m1 = -1e30f, l0 = 0.f, l1 = 0.f;
#pragma unroll 1
            for (int c = 0; c < 2; ++c) {
                float s[16][4];
#pragma unroll
                for (int nt = 0; nt < 16; ++nt) {
                    uint32_t b0, b1;
                    ldsm_x2(b0, b1, sbase + 2 * (KI_OFF + (128 * c + 8 * nt) * PADH + hq + offB2));
                    s[nt][0] = s[nt][1] = s[nt][2] = s[nt][3] = 0.f;
                    mma16(s[nt], a0, a1, a2, a3, b0, b1);
                }
                float cm0 = -1e30f, cm1 = -1e30f;
#pragma unroll
                for (int nt = 0; nt < 16; ++nt) {
                    cm0 = fmaxf(cm0, fmaxf(s[nt][0], s[nt][1]));
                    cm1 = fmaxf(cm1, fmaxf(s[nt][2], s[nt][3]));
                }
                cm0 = fmaxf(cm0, __shfl_xor_sync(0xffffffffu, cm0, 1));
                cm0 = fmaxf(cm0, __shfl_xor_sync(0xffffffffu, cm0, 2));
                cm1 = fmaxf(cm1, __shfl_xor_sync(0xffffffffu, cm1, 1));
                cm1 = fmaxf(cm1, __shfl_xor_sync(0xffffffffu, cm1, 2));
                float nm0 = fmaxf(m0, cm0), nm1 = fmaxf(m1, cm1);
                float sc0 = __expf(m0 - nm0), sc1 = __expf(m1 - nm1);
                l0 *= sc0; l1 *= sc1;
#pragma unroll
                for (int nt2 = 0; nt2 < 2; ++nt2) {
                    o[nt2][0] *= sc0; o[nt2][1] *= sc0;
                    o[nt2][2] *= sc1; o[nt2][3] *= sc1;
                }
                float cl0 = 0.f, cl1 = 0.f;
#pragma unroll
                for (int nt = 0; nt < 16; ++nt) {
                    s[nt][0] = __expf(s[nt][0] - nm0); cl0 += s[nt][0];
                    s[nt][1] = __expf(s[nt][1] - nm0); cl0 += s[nt][1];
                    s[nt][2] = __expf(s[nt][2] - nm1); cl1 += s[nt][2];
                    s[nt][3] = __expf(s[nt][3] - nm1); cl1 += s[nt][3];
                }
                cl0 += __shfl_xor_sync(0xffffffffu, cl0, 1);
                cl0 += __shfl_xor_sync(0xffffffffu, cl0, 2);
                cl1 += __shfl_xor_sync(0xffffffffu, cl1, 1);
                cl1 += __shfl_xor_sync(0xffffffffu, cl1, 2);
                l0 += cl0; l1 += cl1;
                m0 = nm0; m1 = nm1;
                // AV accumulate over this chunk
#pragma unroll
                for (int kc = 0; kc < 8; ++kc) {
                    uint32_t pa0 = packh2(s[2*kc][0], s[2*kc][1]);
                    uint32_t pa1 = packh2(s[2*kc][2], s[2*kc][3]);
                    uint32_t pa2 = packh2(s[2*kc+1][0], s[2*kc+1][1]);
                    uint32_t pa3 = packh2(s[2*kc+1][2], s[2*kc+1][3]);
#pragma unroll
                    for (int nt2 = 0; nt2 < 2; ++nt2) {
                        uint32_t b0, b1;
                        ldsm_x2t(b0, b1, sbase + 2 * (VI_OFF + (128 * c + 16 * kc) * PADH + hq + 8 * nt2 + offB2t));
                        mma16(o[nt2], pa0, pa1, pa2, pa3, b0, b1);
                    }
                }
            }
            const float inv0 = 1.f / l0, inv1 = 1.f / l1;
            // write normalized output back into the Q buffer (race-free per warp mapping)
#pragma unroll
            for (int nt2 = 0; nt2 < 2; ++nt2) {
                const int n0 = hq + 8 * nt2 + 2 * cc;
                *(half2*)(hsm + QI_OFF + (arow + r) * PADH + n0) =
                    __floats2half2_rn(o[nt2][0] * inv0, o[nt2][1] * inv0);
                *(half2*)(hsm + QI_OFF + (arow + r + 8) * PADH + n0) =
                    __floats2half2_rn(o[nt2][2] * inv1, o[nt2][3] * inv1);
            }
        }
    }
    __syncthreads();

    // ---- O projection (+bias) -> g_inter ----
    {
        uint32_t xa[4][4];
#pragma unroll
        for (int kt = 0; kt < 4; ++kt)
            ldsm_x4(xa[kt][0], xa[kt][1], xa[kt][2], xa[kt][3],
                    sbase + 2 * (QI_OFF + 16 * mt * PADH + 16 * kt + offA));
        const uint2* wf = (const uint2*)g_wfrag[4];
        float acc[4][4] = {};
#pragma unroll
        for (int nt = 0; nt < 4; ++nt) {
            const int ntg = 4 * nq + nt;
#pragma unroll
            for (int kt = 0; kt < 4; ++kt) {
                uint2 f = wf[(ntg * 4 + kt) * 32 + lane];
                mma16(acc[nt], xa[kt][0], xa[kt][1], xa[kt][2], xa[kt][3], f.x, f.y);
            }
        }
        const int row0 = 16 * mt + r;
        float* dst = g_inter + ((size_t)b * GG + qc * 64) * DD;
#pragma unroll
        for (int nt = 0; nt < 4; ++nt) {
            const int n0 = 32 * nq + 8 * nt;
            float b0v = bo[n0 + 2 * cc], b1v = bo[n0 + 2 * cc + 1];
            *(float2*)(dst + row0 * DD + n0 + 2 * cc) =
                make_float2(acc[nt][0] + b0v, acc[nt][1] + b1v);
            *(float2*)(dst + (row0 + 8) * DD + n0 + 2 * cc) =
                make_float2(acc[nt][2] + b0v, acc[nt][3] + b1v);
        }
    }
}

// ---------------- Kernel 4: broadcast-add inter, scattered ----------------
__global__ __launch_bounds__(256) void add_scatter_kernel(
    const int* __restrict__ part, float* __restrict__ out)
{
    __shared__ __align__(16) float iv[64];
    __shared__ int toks[64];
    const int tid = threadIdx.x;
    const int b = blockIdx.x >> 8;
    const int g = blockIdx.x & 255;
    if (tid < 64) iv[tid] = g_inter[((size_t)b * GG + g) * DD + tid];
    else if (tid < 128) toks[tid - 64] = part[(size_t)g * CC + (tid - 64)];
    __syncthreads();
#pragma unroll
    for (int k = 0; k < 4; ++k) {
        int f = tid + 256 * k;
        int row = f >> 4, c4 = f & 15;
        float* p = out + ((size_t)b * NTOK + toks[row]) * DD + 4 * c4;
        float4 v = *(float4*)p;
        float4 a = *(const float4*)&iv[4 * c4];
        v.x += a.x; v.y += a.y; v.z += a.z; v.w += a.w;
        *(float4*)p = v;
    }
}

// ---------------- launch ----------------
extern "C" void kernel_launch(void* const* d_in, const int* in_sizes, int n_in,
                              void* d_out, int out_size)
{
    (void)in_sizes; (void)n_in; (void)out_size;
    const float* x    = (const float*)d_in[0];
    const int*   part = (const int*)d_in[1];   // int32 on device (JAX x64 disabled)
    const float* Wq_a = (const float*)d_in[2];
    const float* bq_a = (const float*)d_in[3];
    const float* Wk_a = (const float*)d_in[4];
    const float* bk_a = (const float*)d_in[5];
    const float* Wv_a = (const float*)d_in[6];
    const float* bv_a = (const float*)d_in[7];
    const float* Wo_a = (const float*)d_in[8];
    const float* bo_a = (const float*)d_in[9];
    const float* Wq_i = (const float*)d_in[10];
    const float* bq_i = (const float*)d_in[11];
    const float* Wk_i = (const float*)d_in[12];
    const float* bk_i = (const float*)d_in[13];
    const float* Wv_i = (const float*)d_in[14];
    const float* bv_i = (const float*)d_in[15];
    const float* Wo_i = (const float*)d_in[16];
    const float* bo_i = (const float*)d_in[17];
    float* out = (float*)d_out;

    const int smem_intra = SMEM_INTRA_BYTES;   // 36864 B
    const int smem_iatt  = SMEM_IATT_BYTES;    // 82944 B
    cudaFuncSetAttribute(intra_kernel, cudaFuncAttributeMaxDynamicSharedMemorySize, smem_intra);
    cudaFuncSetAttribute(inter_attn_mma, cudaFuncAttributeMaxDynamicSharedMemorySize, smem_iatt);

    prep_w_kernel<<<40, 256>>>(Wq_a, Wk_a, Wv_a, Wo_a, Wo_i);
    intra_kernel<<<BB * GG, 256, smem_intra>>>(x, part,
        bq_a, bk_a, bv_a, bo_a, out);
    inter_qkv_kernel<<<192, 256>>>(Wq_i, bq_i, Wk_i, bk_i, Wv_i, bv_i);
    inter_attn_mma<<<64, 256, smem_iatt>>>(bo_i);
    add_scatter_kernel<<<BB * GG, 256>>>(part, out);
}

// round 12
// speedup vs baseline: 4.7070x; 1.1357x over previous
#include <cuda_runtime.h>
#include <cuda_fp16.h>
#include <cstdint>

// Problem constants (fixed by the dataset)
constexpr int BB   = 16;     // batch
constexpr int NTOK = 16384;  // tokens
constexpr int DD   = 64;     // model dim (= dhf)
constexpr int GG   = 256;    // groups
constexpr int CC   = 64;     // tokens per group
constexpr int NH   = 4;      // heads
// SCALE = 4.0 multiplies scores; folded into Q at fp16 staging (exact: power of two)

#define PADH 72   // half-precision smem row stride (144 B, ldmatrix conflict-free)
#define LDSF 68   // fp32 smem row stride (pooled-max stash)

// intra smem layout (half indices)
#define XH_OFF 0
#define QH_OFF 4608
#define KH_OFF 9216
#define VH_OFF 13824
#define SMEM_INTRA_BYTES (4 * 4608 * 2)   // 36864 B

// inter-attn smem layout (half indices)
#define PI_OFF  0
#define KI_OFF  18432
#define VI_OFF  36864
#define QI_OFF  55296
#define SMEM_IATT_BYTES ((55296 + 4608) * 2)   // 119808 B

// ---------------- scratch (no allocations allowed) ----------------
__device__ float  g_pooled[BB * GG * DD];          // 1 MiB
__device__ float  g_inter[BB * GG * DD];           // 1 MiB
__device__ __half g_intra[BB * GG * CC * DD];      // 32 MiB (fp16 intra result)
// pre-packed fp16 weight fragments: [mat][(ntg*4+kt)*64 + 2*lane + j]
// mats: 0=Wq_a 1=Wk_a 2=Wv_a 3=Wo_a 4=Wq_i 5=Wk_i 6=Wv_i 7=Wo_i
__device__ uint32_t g_wfrag[8][2048];              // 64 KiB

// ---------------- mma / ldmatrix helpers ----------------
__device__ __forceinline__ void ldsm_x4(uint32_t& r0, uint32_t& r1, uint32_t& r2, uint32_t& r3, uint32_t a) {
    asm volatile("ldmatrix.sync.aligned.m8n8.x4.shared.b16 {%0,%1,%2,%3}, [%4];"
        : "=r"(r0), "=r"(r1), "=r"(r2), "=r"(r3) : "r"(a));
}
__device__ __forceinline__ void ldsm_x2(uint32_t& r0, uint32_t& r1, uint32_t a) {
    asm volatile("ldmatrix.sync.aligned.m8n8.x2.shared.b16 {%0,%1}, [%2];"
        : "=r"(r0), "=r"(r1) : "r"(a));
}
__device__ __forceinline__ void ldsm_x2t(uint32_t& r0, uint32_t& r1, uint32_t a) {
    asm volatile("ldmatrix.sync.aligned.m8n8.x2.trans.shared.b16 {%0,%1}, [%2];"
        : "=r"(r0), "=r"(r1) : "r"(a));
}
__device__ __forceinline__ void mma16(float c[4],
    uint32_t a0, uint32_t a1, uint32_t a2, uint32_t a3, uint32_t b0, uint32_t b1) {
    asm volatile("mma.sync.aligned.m16n8k16.row.col.f32.f16.f16.f32 "
        "{%0,%1,%2,%3}, {%4,%5,%6,%7}, {%8,%9}, {%0,%1,%2,%3};"
        : "+f"(c[0]), "+f"(c[1]), "+f"(c[2]), "+f"(c[3])
        : "r"(a0), "r"(a1), "r"(a2), "r"(a3), "r"(b0), "r"(b1));
}
// pack two fp32 into one fp16x2 register: lo = a, hi = b
__device__ __forceinline__ uint32_t packh2(float a, float b) {
    uint32_t u;
    asm("cvt.rn.f16x2.f32 %0, %1, %2;" : "=r"(u) : "f"(b), "f"(a));
    return u;
}

// ---------------- Kernel 0: pack weights into B-fragment layout ----------------
// grid = 64 x 256: idx over 8 mats x 2048 uint32
__global__ __launch_bounds__(256) void prep_w_kernel(
    const float* __restrict__ Wqa, const float* __restrict__ Wka,
    const float* __restrict__ Wva, const float* __restrict__ Woa,
    const float* __restrict__ Wqi, const float* __restrict__ Wki,
    const float* __restrict__ Wvi, const float* __restrict__ Woi)
{
    const int idx = blockIdx.x * 256 + threadIdx.x;   // 0..16383
    const int mat = idx >> 11;
    const int t   = idx & 2047;
    const int lane2 = t & 63;        // 2*lane + j
    const int j = lane2 & 1, l = lane2 >> 1;
    const int tile = t >> 6;         // ntg*4 + kt
    const int kt = tile & 3, ntg = tile >> 2;
    const float* W =
        (mat == 0) ? Wqa : (mat == 1) ? Wka : (mat == 2) ? Wva : (mat == 3) ? Woa :
        (mat == 4) ? Wqi : (mat == 5) ? Wki : (mat == 6) ? Wvi : Woi;
    const int row = 8 * ntg + (l >> 2);
    const int col = 16 * kt + 8 * j + 2 * (l & 3);
    g_wfrag[mat][t] = packh2(W[row * 64 + col], W[row * 64 + col + 1]);
}

// ---------------- Kernel 1: intra-group MHA (fp16 mma, global weight frags) ----------------
// grid = 4096 (b*256+g), 256 threads = 8 warps, dyn smem = 36864 B
__global__ __launch_bounds__(256, 3) void intra_kernel(
    const float* __restrict__ x, const int* __restrict__ part,
    const float* __restrict__ bq, const float* __restrict__ bk,
    const float* __restrict__ bv, const float* __restrict__ bo)
{
    extern __shared__ __half hsm[];
    float* stash = (float*)(hsm + QH_OFF);   // 64 x LDSF fp32 overlay (dead Q/K)

    const int tid = threadIdx.x;
    const int bb = blockIdx.x >> 8;
    const int g  = blockIdx.x & 255;
    const int* pg = part + (size_t)g * CC;
    const float* xb = x + (size_t)bb * NTOK * DD;

    const int lane = tid & 31, w = tid >> 5;
    const int mt = w & 3, nq = w >> 2;
    const int r  = lane >> 2, cc = lane & 3;
    const int ln = lane & 7, sel = lane >> 3;
    const int offA   = (ln + 8 * (sel & 1)) * PADH + 8 * (sel >> 1);
    const int offB2  = ln * PADH + 8 * (sel & 1);
    const int offB2t = (lane & 15) * PADH;

    const uint32_t sbase = (uint32_t)__cvta_generic_to_shared(hsm);

    // ---- gather x (fp32 -> half) ----
#pragma unroll
    for (int k = 0; k < 4; ++k) {
        int f = tid + 256 * k;
        int row = f >> 4, c4 = f & 15;
        int tok = pg[row];
        float4 v = ((const float4*)(xb + (size_t)tok * DD))[c4];
        __half* d = hsm + XH_OFF + row * PADH + 4 * c4;
        *(half2*)(d)     = __floats2half2_rn(v.x, v.y);
        *(half2*)(d + 2) = __floats2half2_rn(v.z, v.w);
    }
    __syncthreads();

    // ---- A fragments of xs: shared by Q, K, V projections ----
    uint32_t xa[4][4];
#pragma unroll
    for (int kt = 0; kt < 4; ++kt)
        ldsm_x4(xa[kt][0], xa[kt][1], xa[kt][2], xa[kt][3],
                sbase + 2 * (XH_OFF + 16 * mt * PADH + 16 * kt + offA));

    const int row0 = 16 * mt + r;

    auto projG = [&](int mat, const float* __restrict__ bias, int Doff, float scl) {
        const uint2* wf = (const uint2*)g_wfrag[mat];
        float acc[4][4] = {};
#pragma unroll
        for (int nt = 0; nt < 4; ++nt) {
            const int ntg = 4 * nq + nt;
#pragma unroll
            for (int kt = 0; kt < 4; ++kt) {
                uint2 f = wf[(ntg * 4 + kt) * 32 + lane];
                mma16(acc[nt], xa[kt][0], xa[kt][1], xa[kt][2], xa[kt][3], f.x, f.y);
            }
        }
#pragma unroll
        for (int nt = 0; nt < 4; ++nt) {
            const int n0 = 32 * nq + 8 * nt;
            float b0v = bias[n0 + 2 * cc], b1v = bias[n0 + 2 * cc + 1];
            *(half2*)(hsm + Doff + row0 * PADH + n0 + 2 * cc) =
                __floats2half2_rn((acc[nt][0] + b0v) * scl, (acc[nt][1] + b1v) * scl);
            *(half2*)(hsm + Doff + (row0 + 8) * PADH + n0 + 2 * cc) =
                __floats2half2_rn((acc[nt][2] + b0v) * scl, (acc[nt][3] + b1v) * scl);
        }
    };

    projG(0, bq, QH_OFF, 4.0f);
    projG(1, bk, KH_OFF, 1.0f);
    projG(2, bv, VH_OFF, 1.0f);
    __syncthreads();

    // ---- attention, register-resident ----
    {
        const int hsel = w >> 2;
        const int arow = 16 * mt;
#pragma unroll
        for (int hp = 0; hp < 2; ++hp) {
            const int h = 2 * hp + hsel;
            const int hq = 16 * h;
            uint32_t a0, a1, a2, a3;
            ldsm_x4(a0, a1, a2, a3, sbase + 2 * (QH_OFF + arow * PADH + hq + offA));
            float s[8][4];
#pragma unroll
            for (int nt = 0; nt < 8; ++nt) {
                uint32_t b0, b1;
                ldsm_x2(b0, b1, sbase + 2 * (KH_OFF + 8 * nt * PADH + hq + offB2));
                s[nt][0] = s[nt][1] = s[nt][2] = s[nt][3] = 0.f;
                mma16(s[nt], a0, a1, a2, a3, b0, b1);
            }
            float mx0 = -1e30f, mx1 = -1e30f;
#pragma unroll
            for (int nt = 0; nt < 8; ++nt) {
                mx0 = fmaxf(mx0, fmaxf(s[nt][0], s[nt][1]));
                mx1 = fmaxf(mx1, fmaxf(s[nt][2], s[nt][3]));
            }
            mx0 = fmaxf(mx0, __shfl_xor_sync(0xffffffffu, mx0, 1));
            mx0 = fmaxf(mx0, __shfl_xor_sync(0xffffffffu, mx0, 2));
            mx1 = fmaxf(mx1, __shfl_xor_sync(0xffffffffu, mx1, 1));
            mx1 = fmaxf(mx1, __shfl_xor_sync(0xffffffffu, mx1, 2));
            float sum0 = 0.f, sum1 = 0.f;
#pragma unroll
            for (int nt = 0; nt < 8; ++nt) {
                s[nt][0] = __expf(s[nt][0] - mx0); sum0 += s[nt][0];
                s[nt][1] = __expf(s[nt][1] - mx0); sum0 += s[nt][1];
                s[nt][2] = __expf(s[nt][2] - mx1); sum1 += s[nt][2];
                s[nt][3] = __expf(s[nt][3] - mx1); sum1 += s[nt][3];
            }
            sum0 += __shfl_xor_sync(0xffffffffu, sum0, 1);
            sum0 += __shfl_xor_sync(0xffffffffu, sum0, 2);
            sum1 += __shfl_xor_sync(0xffffffffu, sum1, 1);
            sum1 += __shfl_xor_sync(0xffffffffu, sum1, 2);
            const float inv0 = 1.f / sum0, inv1 = 1.f / sum1;
            float o[2][4] = {};
#pragma unroll
            for (int kc = 0; kc < 4; ++kc) {
                uint32_t pa0 = packh2(s[2*kc][0] * inv0, s[2*kc][1] * inv0);
                uint32_t pa1 = packh2(s[2*kc][2] * inv1, s[2*kc][3] * inv1);
                uint32_t pa2 = packh2(s[2*kc+1][0] * inv0, s[2*kc+1][1] * inv0);
                uint32_t pa3 = packh2(s[2*kc+1][2] * inv1, s[2*kc+1][3] * inv1);
#pragma unroll
                for (int nt2 = 0; nt2 < 2; ++nt2) {
                    uint32_t b0, b1;
                    ldsm_x2t(b0, b1, sbase + 2 * (VH_OFF + 16 * kc * PADH + hq + 8 * nt2 + offB2t));
                    mma16(o[nt2], pa0, pa1, pa2, pa3, b0, b1);
                }
            }
#pragma unroll
            for (int nt2 = 0; nt2 < 2; ++nt2) {
                const int n0 = hq + 8 * nt2 + 2 * cc;
                *(half2*)(hsm + XH_OFF + (arow + r) * PADH + n0) =
                    __floats2half2_rn(o[nt2][0], o[nt2][1]);
                *(half2*)(hsm + XH_OFF + (arow + r + 8) * PADH + n0) =
                    __floats2half2_rn(o[nt2][2], o[nt2][3]);
            }
        }
    }
    __syncthreads();

    // ---- O projection (+bias) -> fp16 g_intra (coalesced) + fp32 stash -> pooled max ----
    {
#pragma unroll
        for (int kt = 0; kt < 4; ++kt)
            ldsm_x4(xa[kt][0], xa[kt][1], xa[kt][2], xa[kt][3],
                    sbase + 2 * (XH_OFF + 16 * mt * PADH + 16 * kt + offA));
        const uint2* wf = (const uint2*)g_wfrag[3];
        float acc[4][4] = {};
#pragma unroll
        for (int nt = 0; nt < 4; ++nt) {
            const int ntg = 4 * nq + nt;
#pragma unroll
            for (int kt = 0; kt < 4; ++kt) {
                uint2 f = wf[(ntg * 4 + kt) * 32 + lane];
                mma16(acc[nt], xa[kt][0], xa[kt][1], xa[kt][2], xa[kt][3], f.x, f.y);
            }
        }
        __half* dI = g_intra + ((size_t)(bb * GG + g) * CC) * DD;
#pragma unroll
        for (int nt = 0; nt < 4; ++nt) {
            const int n0 = 32 * nq + 8 * nt;
            float b0v = bo[n0 + 2 * cc], b1v = bo[n0 + 2 * cc + 1];
            float v0 = acc[nt][0] + b0v, v1 = acc[nt][1] + b1v;
            float v2 = acc[nt][2] + b0v, v3 = acc[nt][3] + b1v;
            *(half2*)(dI + row0 * DD + n0 + 2 * cc)       = __floats2half2_rn(v0, v1);
            *(half2*)(dI + (row0 + 8) * DD + n0 + 2 * cc) = __floats2half2_rn(v2, v3);
            *(float2*)&stash[row0 * LDSF + n0 + 2 * cc]       = make_float2(v0, v1);
            *(float2*)&stash[(row0 + 8) * LDSF + n0 + 2 * cc] = make_float2(v2, v3);
        }
    }
    __syncthreads();
    if (tid < 64) {
        float m = stash[tid];
#pragma unroll 8
        for (int n = 1; n < 64; ++n) m = fmaxf(m, stash[n * LDSF + tid]);
        g_pooled[((size_t)bb * GG + g) * DD + tid] = m;
    }
}

// ---------------- Kernel 2: fused inter QKV + flash attention + O-proj ----------------
// grid = 64 (b = blk>>2, qchunk = blk&3), 256 threads = 8 warps, dyn smem = 119808 B
__global__ __launch_bounds__(256) void inter_attn_mma(
    const float* __restrict__ bq, const float* __restrict__ bk,
    const float* __restrict__ bv, const float* __restrict__ bo)
{
    extern __shared__ __half hsm[];
    const int tid = threadIdx.x;
    const int b  = blockIdx.x >> 2;
    const int qc = blockIdx.x & 3;

    const int lane = tid & 31, w = tid >> 5;
    const int mt = w & 3, nq = w >> 2;
    const int r  = lane >> 2, cc = lane & 3;
    const int ln = lane & 7, sel = lane >> 3;
    const int offA   = (ln + 8 * (sel & 1)) * PADH + 8 * (sel >> 1);
    const int offB2  = ln * PADH + 8 * (sel & 1);
    const int offB2t = (lane & 15) * PADH;
    const uint32_t sbase = (uint32_t)__cvta_generic_to_shared(hsm);

    const float* pb = g_pooled + (size_t)b * GG * DD;

    // ---- stage pooled (256 x 64) as fp16 ----
#pragma unroll
    for (int k = 0; k < 16; ++k) {
        int f = tid + 256 * k;
        int row = f >> 4, c4 = f & 15;
        float4 v = ((const float4*)(pb + row * 64))[c4];
        __half* d = hsm + PI_OFF + row * PADH + 4 * c4;
        *(half2*)(d)     = __floats2half2_rn(v.x, v.y);
        *(half2*)(d + 2) = __floats2half2_rn(v.z, v.w);
    }
    __syncthreads();

    // ---- K, V projections over all 256 rows; Q over own 64 rows ----
    {
        const uint2* wfK = (const uint2*)g_wfrag[5];
        const uint2* wfV = (const uint2*)g_wfrag[6];
#pragma unroll
        for (int hf = 0; hf < 2; ++hf) {
            const int rt = w + 8 * hf;   // row tile 0..15
            uint32_t pa[4][4];
#pragma unroll
            for (int kt = 0; kt < 4; ++kt)
                ldsm_x4(pa[kt][0], pa[kt][1], pa[kt][2], pa[kt][3],
                        sbase + 2 * (PI_OFF + 16 * rt * PADH + 16 * kt + offA));
            const int rr0 = 16 * rt + r;
#pragma unroll
            for (int ng = 0; ng < 8; ++ng) {
                float ak[4] = {}, av[4] = {};
#pragma unroll
                for (int kt = 0; kt < 4; ++kt) {
                    uint2 fk = wfK[(ng * 4 + kt) * 32 + lane];
                    uint2 fv = wfV[(ng * 4 + kt) * 32 + lane];
                    mma16(ak, pa[kt][0], pa[kt][1], pa[kt][2], pa[kt][3], fk.x, fk.y);
                    mma16(av, pa[kt][0], pa[kt][1], pa[kt][2], pa[kt][3], fv.x, fv.y);
                }
                const int n0 = 8 * ng;
                float bk0 = bk[n0 + 2 * cc], bk1 = bk[n0 + 2 * cc + 1];
                float bv0 = bv[n0 + 2 * cc], bv1 = bv[n0 + 2 * cc + 1];
                *(half2*)(hsm + KI_OFF + rr0 * PADH + n0 + 2 * cc) =
                    __floats2half2_rn(ak[0] + bk0, ak[1] + bk1);
                *(half2*)(hsm + KI_OFF + (rr0 + 8) * PADH + n0 + 2 * cc) =
                    __floats2half2_rn(ak[2] + bk0, ak[3] + bk1);
                *(half2*)(hsm + VI_OFF + rr0 * PADH + n0 + 2 * cc) =
                    __floats2half2_rn(av[0] + bv0, av[1] + bv1);
                *(half2*)(hsm + VI_OFF + (rr0 + 8) * PADH + n0 + 2 * cc) =
                    __floats2half2_rn(av[2] + bv0, av[3] + bv1);
            }
        }
        // Q for own chunk (pooled rows qc*64..): tile 4*qc + mt, cols 32*nq..
        const uint2* wfQ = (const uint2*)g_wfrag[4];
        const int qt = 4 * qc + mt;
        uint32_t pa[4][4];
#pragma unroll
        for (int kt = 0; kt < 4; ++kt)
            ldsm_x4(pa[kt][0], pa[kt][1], pa[kt][2], pa[kt][3],
                    sbase + 2 * (PI_OFF + 16 * qt * PADH + 16 * kt + offA));
        float acc[4][4] = {};
#pragma unroll
        for (int nt = 0; nt < 4; ++nt) {
            const int ntg = 4 * nq + nt;
#pragma unroll
            for (int kt = 0; kt < 4; ++kt) {
                uint2 f = wfQ[(ntg * 4 + kt) * 32 + lane];
                mma16(acc[nt], pa[kt][0], pa[kt][1], pa[kt][2], pa[kt][3], f.x, f.y);
            }
        }
        const int lrow0 = 16 * mt + r;
#pragma unroll
        for (int nt = 0; nt < 4; ++nt) {
            const int n0 = 32 * nq + 8 * nt;
            float b0v = bq[n0 + 2 * cc], b1v = bq[n0 + 2 * cc + 1];
            *(half2*)(hsm + QI_OFF + lrow0 * PADH + n0 + 2 * cc) =
                __floats2half2_rn((acc[nt][0] + b0v) * 4.f, (acc[nt][1] + b1v) * 4.f);
            *(half2*)(hsm + QI_OFF + (lrow0 + 8) * PADH + n0 + 2 * cc) =
                __floats2half2_rn((acc[nt][2] + b0v) * 4.f, (acc[nt][3] + b1v) * 4.f);
        }
    }
    __syncthreads();

    // ---- flash attention: warp = (mt rows, hsel head-pair), 256 keys in 2 chunks ----
    {
        const int hsel = w >> 2;
        const int arow = 16 * mt;
#pragma unroll 1
        for (int hp = 0; hp < 2; ++hp) {
            const int h = 2 * hp + hsel;
            const int hq = 16 * h;
            uint32_t a0, a1, a2, a3;
            ldsm_x4(a0, a1, a2, a3, sbase + 2 * (QI_OFF + arow * PADH + hq + offA));
            float o[2][4] = {};
            float m0 = -1e30f, m1 = -1e30f, l0 = 0.f, l1 = 0.f;
#pragma unroll 1
            for (int c = 0; c < 2; ++c) {
                float s[16][4];
#pragma unroll
                for (int nt = 0; nt < 16; ++nt) {
                    uint32_t b0, b1;
                    ldsm_x2(b0, b1, sbase + 2 * (KI_OFF + (128 * c + 8 * nt) * PADH + hq + offB2));
                    s[nt][0] = s[nt][1] = s[nt][2] = s[nt][3] = 0.f;
                    mma16(s[nt], a0, a1, a2, a3, b0, b1);
                }
                float cm0 = -1e30f, cm1 = -1e30f;
#pragma unroll
                for (int nt = 0; nt < 16; ++nt) {
                    cm0 = fmaxf(cm0, fmaxf(s[nt][0], s[nt][1]));
                    cm1 = fmaxf(cm1, fmaxf(s[nt][2], s[nt][3]));
                }
                cm0 = fmaxf(cm0, __shfl_xor_sync(0xffffffffu, cm0, 1));
                cm0 = fmaxf(cm0, __shfl_xor_sync(0xffffffffu, cm0, 2));
                cm1 = fmaxf(cm1, __shfl_xor_sync(0xffffffffu, cm1, 1));
                cm1 = fmaxf(cm1, __shfl_xor_sync(0xffffffffu, cm1, 2));
                float nm0 = fmaxf(m0, cm0), nm1 = fmaxf(m1, cm1);
                float sc0 = __expf(m0 - nm0), sc1 = __expf(m1 - nm1);
                l0 *= sc0; l1 *= sc1;
#pragma unroll
                for (int nt2 = 0; nt2 < 2; ++nt2) {
                    o[nt2][0] *= sc0; o[nt2][1] *= sc0;
                    o[nt2][2] *= sc1; o[nt2][3] *= sc1;
                }
                float cl0 = 0.f, cl1 = 0.f;
#pragma unroll
                for (int nt = 0; nt < 16; ++nt) {
                    s[nt][0] = __expf(s[nt][0] - nm0); cl0 += s[nt][0];
                    s[nt][1] = __expf(s[nt][1] - nm0); cl0 += s[nt][1];
                    s[nt][2] = __expf(s[nt][2] - nm1); cl1 += s[nt][2];
                    s[nt][3] = __expf(s[nt][3] - nm1); cl1 += s[nt][3];
                }
                cl0 += __shfl_xor_sync(0xffffffffu, cl0, 1);
                cl0 += __shfl_xor_sync(0xffffffffu, cl0, 2);
                cl1 += __shfl_xor_sync(0xffffffffu, cl1, 1);
                cl1 += __shfl_xor_sync(0xffffffffu, cl1, 2);
                l0 += cl0; l1 += cl1;
                m0 = nm0; m1 = nm1;
#pragma unroll
                for (int kc = 0; kc < 8; ++kc) {
                    uint32_t pa0 = packh2(s[2*kc][0], s[2*kc][1]);
                    uint32_t pa1 = packh2(s[2*kc][2], s[2*kc][3]);
                    uint32_t pa2 = packh2(s[2*kc+1][0], s[2*kc+1][1]);
                    uint32_t pa3 = packh2(s[2*kc+1][2], s[2*kc+1][3]);
#pragma unroll
                    for (int nt2 = 0; nt2 < 2; ++nt2) {
                        uint32_t b0, b1;
                        ldsm_x2t(b0, b1, sbase + 2 * (VI_OFF + (128 * c + 16 * kc) * PADH + hq + 8 * nt2 + offB2t));
                        mma16(o[nt2], pa0, pa1, pa2, pa3, b0, b1);
                    }
                }
            }
            const float inv0 = 1.f / l0, inv1 = 1.f / l1;
#pragma unroll
            for (int nt2 = 0; nt2 < 2; ++nt2) {
                const int n0 = hq + 8 * nt2 + 2 * cc;
                *(half2*)(hsm + QI_OFF + (arow + r) * PADH + n0) =
                    __floats2half2_rn(o[nt2][0] * inv0, o[nt2][1] * inv0);
                *(half2*)(hsm + QI_OFF + (arow + r + 8) * PADH + n0) =
                    __floats2half2_rn(o[nt2][2] * inv1, o[nt2][3] * inv1);
            }
        }
    }
    __syncthreads();

    // ---- O projection (+bias) -> g_inter ----
    {
        uint32_t xa[4][4];
#pragma unroll
        for (int kt = 0; kt < 4; ++kt)
            ldsm_x4(xa[kt][0], xa[kt][1], xa[kt][2], xa[kt][3],
                    sbase + 2 * (QI_OFF + 16 * mt * PADH + 16 * kt + offA));
        const uint2* wf = (const uint2*)g_wfrag[7];
        float acc[4][4] = {};
#pragma unroll
        for (int nt = 0; nt < 4; ++nt) {
            const int ntg = 4 * nq + nt;
#pragma unroll
            for (int kt = 0; kt < 4; ++kt) {
                uint2 f = wf[(ntg * 4 + kt) * 32 + lane];
                mma16(acc[nt], xa[kt][0], xa[kt][1], xa[kt][2], xa[kt][3], f.x, f.y);
            }
        }
        const int row0 = 16 * mt + r;
        float* dst = g_inter + ((size_t)b * GG + qc * 64) * DD;
#pragma unroll
        for (int nt = 0; nt < 4; ++nt) {
            const int n0 = 32 * nq + 8 * nt;
            float b0v = bo[n0 + 2 * cc], b1v = bo[n0 + 2 * cc + 1];
            *(float2*)(dst + row0 * DD + n0 + 2 * cc) =
                make_float2(acc[nt][0] + b0v, acc[nt][1] + b1v);
            *(float2*)(dst + (row0 + 8) * DD + n0 + 2 * cc) =
                make_float2(acc[nt][2] + b0v, acc[nt][3] + b1v);
        }
    }
}

// ---------------- Kernel 3: final add + scatter (only writer of out) ----------------
// grid = 4096 (b*256+g), 256 threads
__global__ __launch_bounds__(256) void final_scatter_kernel(
    const int* __restrict__ part, float* __restrict__ out)
{
    __shared__ __align__(16) float iv[64];
    __shared__ int toks[64];
    const int tid = threadIdx.x;
    const int b = blockIdx.x >> 8;
    const int g = blockIdx.x & 255;
    if (tid < 64) iv[tid] = g_inter[((size_t)b * GG + g) * DD + tid];
    else if (tid < 128) toks[tid - 64] = part[(size_t)g * CC + (tid - 64)];
    __syncthreads();
    const __half* src = g_intra + ((size_t)(b * GG + g) * CC) * DD;
#pragma unroll
    for (int k = 0; k < 4; ++k) {
        int f = tid + 256 * k;
        int row = f >> 4, c4 = f & 15;
        half2 h0 = *(const half2*)(src + row * DD + 4 * c4);
        half2 h1 = *(const half2*)(src + row * DD + 4 * c4 + 2);
        float4 a = *(const float4*)&iv[4 * c4];
        float2 f0 = __half22float2(h0), f1 = __half22float2(h1);
        float4 v;
        v.x = f0.x + a.x; v.y = f0.y + a.y;
        v.z = f1.x + a.z; v.w = f1.y + a.w;
        *(float4*)&out[((size_t)b * NTOK + toks[row]) * DD + 4 * c4] = v;
    }
}

// ---------------- launch ----------------
extern "C" void kernel_launch(void* const* d_in, const int* in_sizes, int n_in,
                              void* d_out, int out_size)
{
    (void)in_sizes; (void)n_in; (void)out_size;
    const float* x    = (const float*)d_in[0];
    const int*   part = (const int*)d_in[1];   // int32 on device (JAX x64 disabled)
    const float* Wq_a = (const float*)d_in[2];
    const float* bq_a = (const float*)d_in[3];
    const float* Wk_a = (const float*)d_in[4];
    const float* bk_a = (const float*)d_in[5];
    const float* Wv_a = (const float*)d_in[6];
    const float* bv_a = (const float*)d_in[7];
    const float* Wo_a = (const float*)d_in[8];
    const float* bo_a = (const float*)d_in[9];
    const float* Wq_i = (const float*)d_in[10];
    const float* bq_i = (const float*)d_in[11];
    const float* Wk_i = (const float*)d_in[12];
    const float* bk_i = (const float*)d_in[13];
    const float* Wv_i = (const float*)d_in[14];
    const float* bv_i = (const float*)d_in[15];
    const float* Wo_i = (const float*)d_in[16];
    const float* bo_i = (const float*)d_in[17];
    float* out = (float*)d_out;

    const int smem_intra = SMEM_INTRA_BYTES;   // 36864 B
    const int smem_iatt  = SMEM_IATT_BYTES;    // 119808 B
    cudaFuncSetAttribute(intra_kernel, cudaFuncAttributeMaxDynamicSharedMemorySize, smem_intra);
    cudaFuncSetAttribute(inter_attn_mma, cudaFuncAttributeMaxDynamicSharedMemorySize, smem_iatt);

    prep_w_kernel<<<64, 256>>>(Wq_a, Wk_a, Wv_a, Wo_a, Wq_i, Wk_i, Wv_i, Wo_i);
    intra_kernel<<<BB * GG, 256, smem_intra>>>(x, part, bq_a, bk_a, bv_a, bo_a);
    inter_attn_mma<<<64, 256, smem_iatt>>>(bq_i, bk_i, bv_i, bo_i);
    final_scatter_kernel<<<BB * GG, 256>>>(part, out);
}